// round 1
// baseline (speedup 1.0000x reference)
#include <cuda_runtime.h>
#include <math.h>

// Problem constants
constexpr int kB  = 4;
constexpr int kC  = 512;
constexpr int kHW = 4096;           // h*w = 64*64
constexpr int kG  = 32;
constexpr int kCPG = kC / kG;       // 16
constexpr float kEPS = 1e-6f;

// Scratch (allocation-free rule: __device__ globals)
__device__ float g_h  [(size_t)kB * kC * kHW];
__device__ float g_q  [(size_t)kB * kC * kHW];
__device__ float g_k  [(size_t)kB * kC * kHW];
__device__ float g_v  [(size_t)kB * kC * kHW];
__device__ float g_o2 [(size_t)kB * kC * kHW];
__device__ float g_sim[(size_t)kB * kHW * kHW];   // 256 MB

// ---------------------------------------------------------------------------
// GroupNorm: one block per (batch, group). group = 16 channels x 4096 = 65536.
// ---------------------------------------------------------------------------
__global__ void groupnorm_kernel(const float* __restrict__ x,
                                 const float* __restrict__ gamma,
                                 const float* __restrict__ beta,
                                 float* __restrict__ out) {
    const int grp = blockIdx.x;            // 0 .. kB*kG-1
    const int b = grp / kG, g = grp % kG;
    const float* xp = x  + ((size_t)b * kC + (size_t)g * kCPG) * kHW;
    float*       op = out + ((size_t)b * kC + (size_t)g * kCPG) * kHW;
    const int N = kCPG * kHW;              // 65536

    float s = 0.f, ss = 0.f;
    for (int i = threadIdx.x; i < N; i += blockDim.x) {
        float v = xp[i];
        s += v; ss += v * v;
    }
    __shared__ float sh1[256], sh2[256];
    sh1[threadIdx.x] = s; sh2[threadIdx.x] = ss;
    __syncthreads();
    for (int o = 128; o > 0; o >>= 1) {
        if (threadIdx.x < o) {
            sh1[threadIdx.x] += sh1[threadIdx.x + o];
            sh2[threadIdx.x] += sh2[threadIdx.x + o];
        }
        __syncthreads();
    }
    const float mean = sh1[0] / (float)N;
    const float var  = sh2[0] / (float)N - mean * mean;
    const float rinv = rsqrtf(var + kEPS);

    for (int i = threadIdx.x; i < N; i += blockDim.x) {
        int ch = g * kCPG + i / kHW;
        op[i] = (xp[i] - mean) * rinv * gamma[ch] + beta[ch];
    }
}

// ---------------------------------------------------------------------------
// Tiled SGEMM: C[m][n] = sum_k opA(m,k) * opB(k,n)   (+ epilogue)
//   TA=0: A is [M,K] row-major;  TA=1: A is [K,M] (row stride M)
//   TB=0: B is [K,N] row-major;  TB=1: B is [N,K] (row stride K)
//   EPI=0: + bias[m]
//   EPI=1: * alpha                  (bias unused)
//   EPI=2: + bias[m] + res[m][n]    (residual)
// Block tile 128x128x16, 256 threads, 8x8 per thread.
// All dims assumed multiples of tile sizes (they are for this problem).
// ---------------------------------------------------------------------------
template <int TA, int TB, int EPI>
__global__ void __launch_bounds__(256)
gemm_kernel(const float* __restrict__ A, const float* __restrict__ Bm,
            const float* __restrict__ bias, const float* __restrict__ res,
            float* __restrict__ Cm,
            int M, int N, int K,
            size_t sA, size_t sB, size_t sC,
            float alpha) {
    constexpr int BM = 128, BN = 128, BK = 16;
    __shared__ float As[BK][BM];
    __shared__ float Bs[BK][BN];

    const int bz = blockIdx.z;
    const float* Ab = A  + sA * bz;
    const float* Bb = Bm + sB * bz;
    float*       Cb = Cm + sC * bz;
    const float* Rb = (EPI == 2) ? (res + sC * bz) : nullptr;

    const int m0 = blockIdx.y * BM;
    const int n0 = blockIdx.x * BN;
    const int tid = threadIdx.x;
    const int tx = tid % 16, ty = tid / 16;

    float acc[8][8] = {};

    for (int k0 = 0; k0 < K; k0 += BK) {
        // ---- load A tile into As[k][m] ----
        if (TA) {
            // A[k][m], m contiguous
            int m = (tid % 32) * 4;
            int k = tid / 32;                           // 0..7
            #pragma unroll
            for (int kk = 0; kk < 2; kk++) {
                float4 v = *(const float4*)(Ab + (size_t)(k0 + k + kk * 8) * M + m0 + m);
                *(float4*)(&As[k + kk * 8][m]) = v;
            }
        } else {
            // A[m][k], k contiguous -> transpose into smem
            int k = (tid % 4) * 4;
            int m = tid / 4;                            // 0..63
            #pragma unroll
            for (int mm = 0; mm < 2; mm++) {
                float4 v = *(const float4*)(Ab + (size_t)(m0 + m + mm * 64) * K + k0 + k);
                As[k + 0][m + mm * 64] = v.x;
                As[k + 1][m + mm * 64] = v.y;
                As[k + 2][m + mm * 64] = v.z;
                As[k + 3][m + mm * 64] = v.w;
            }
        }
        // ---- load B tile into Bs[k][n] ----
        if (TB == 0) {
            int n = (tid % 32) * 4;
            int k = tid / 32;
            #pragma unroll
            for (int kk = 0; kk < 2; kk++) {
                float4 v = *(const float4*)(Bb + (size_t)(k0 + k + kk * 8) * N + n0 + n);
                *(float4*)(&Bs[k + kk * 8][n]) = v;
            }
        } else {
            int k = (tid % 4) * 4;
            int n = tid / 4;
            #pragma unroll
            for (int nn = 0; nn < 2; nn++) {
                float4 v = *(const float4*)(Bb + (size_t)(n0 + n + nn * 64) * K + k0 + k);
                Bs[k + 0][n + nn * 64] = v.x;
                Bs[k + 1][n + nn * 64] = v.y;
                Bs[k + 2][n + nn * 64] = v.z;
                Bs[k + 3][n + nn * 64] = v.w;
            }
        }
        __syncthreads();

        #pragma unroll
        for (int k = 0; k < BK; k++) {
            float a[8], b[8];
            *(float4*)&a[0] = *(const float4*)&As[k][ty * 8 + 0];
            *(float4*)&a[4] = *(const float4*)&As[k][ty * 8 + 4];
            *(float4*)&b[0] = *(const float4*)&Bs[k][tx * 8 + 0];
            *(float4*)&b[4] = *(const float4*)&Bs[k][tx * 8 + 4];
            #pragma unroll
            for (int i = 0; i < 8; i++)
                #pragma unroll
                for (int j = 0; j < 8; j++)
                    acc[i][j] += a[i] * b[j];
        }
        __syncthreads();
    }

    // ---- epilogue ----
    #pragma unroll
    for (int i = 0; i < 8; i++) {
        const int m = m0 + ty * 8 + i;
        float bv = 0.f;
        if (EPI != 1) bv = bias[m];
        #pragma unroll
        for (int j = 0; j < 8; j += 4) {
            const int n = n0 + tx * 8 + j;
            float4 r;
            r.x = acc[i][j + 0]; r.y = acc[i][j + 1];
            r.z = acc[i][j + 2]; r.w = acc[i][j + 3];
            if (EPI == 1) {
                r.x *= alpha; r.y *= alpha; r.z *= alpha; r.w *= alpha;
            } else {
                r.x += bv; r.y += bv; r.z += bv; r.w += bv;
            }
            if (EPI == 2) {
                float4 rr = *(const float4*)(Rb + (size_t)m * N + n);
                r.x += rr.x; r.y += rr.y; r.z += rr.z; r.w += rr.w;
            }
            *(float4*)(Cb + (size_t)m * N + n) = r;
        }
    }
}

// ---------------------------------------------------------------------------
// Row softmax over 4096 elements; one block (256 thr) per row; in-place.
// ---------------------------------------------------------------------------
__global__ void softmax_kernel(float* __restrict__ sim) {
    float* p = sim + (size_t)blockIdx.x * kHW;
    const int tid = threadIdx.x;
    float v[16];
    float mx = -1e30f;
    #pragma unroll
    for (int i = 0; i < 16; i++) {
        v[i] = p[tid + i * 256];
        mx = fmaxf(mx, v[i]);
    }
    __shared__ float sh[256];
    sh[tid] = mx; __syncthreads();
    for (int o = 128; o > 0; o >>= 1) {
        if (tid < o) sh[tid] = fmaxf(sh[tid], sh[tid + o]);
        __syncthreads();
    }
    mx = sh[0];
    __syncthreads();
    float s = 0.f;
    #pragma unroll
    for (int i = 0; i < 16; i++) { v[i] = __expf(v[i] - mx); s += v[i]; }
    sh[tid] = s; __syncthreads();
    for (int o = 128; o > 0; o >>= 1) {
        if (tid < o) sh[tid] += sh[tid + o];
        __syncthreads();
    }
    const float rinv = 1.f / sh[0];
    #pragma unroll
    for (int i = 0; i < 16; i++) p[tid + i * 256] = v[i] * rinv;
}

// ---------------------------------------------------------------------------
extern "C" void kernel_launch(void* const* d_in, const int* in_sizes, int n_in,
                              void* d_out, int out_size) {
    const float* x     = (const float*)d_in[0];
    const float* gamma = (const float*)d_in[1];
    const float* beta  = (const float*)d_in[2];
    const float* wq    = (const float*)d_in[3];
    const float* bq    = (const float*)d_in[4];
    const float* wk    = (const float*)d_in[5];
    const float* bk    = (const float*)d_in[6];
    const float* wv    = (const float*)d_in[7];
    const float* bv    = (const float*)d_in[8];
    const float* wo    = (const float*)d_in[9];
    const float* bo    = (const float*)d_in[10];
    float* out = (float*)d_out;

    float *h, *q, *k, *v, *o2, *sim;
    cudaGetSymbolAddress((void**)&h,   g_h);
    cudaGetSymbolAddress((void**)&q,   g_q);
    cudaGetSymbolAddress((void**)&k,   g_k);
    cudaGetSymbolAddress((void**)&v,   g_v);
    cudaGetSymbolAddress((void**)&o2,  g_o2);
    cudaGetSymbolAddress((void**)&sim, g_sim);

    const size_t sCN  = (size_t)kC * kHW;   // per-batch stride for [c, n]
    const size_t sNN  = (size_t)kHW * kHW;  // per-batch stride for sim
    const float  scale = 1.0f / sqrtf((float)kC);

    // 1) GroupNorm -> h  [b, c, n]
    groupnorm_kernel<<<kB * kG, 256>>>(x, gamma, beta, h);

    // 2) Q/K/V projections: [512,512] x [512,4096] per batch
    {
        dim3 grid(kHW / 128, kC / 128, kB);  // (32, 4, 4)
        gemm_kernel<0, 0, 0><<<grid, 256>>>(wq, h, bq, nullptr, q,
                                            kC, kHW, kC, 0, sCN, sCN, 1.f);
        gemm_kernel<0, 0, 0><<<grid, 256>>>(wk, h, bk, nullptr, k,
                                            kC, kHW, kC, 0, sCN, sCN, 1.f);
        gemm_kernel<0, 0, 0><<<grid, 256>>>(wv, h, bv, nullptr, v,
                                            kC, kHW, kC, 0, sCN, sCN, 1.f);
    }

    // 3) sim = (Q^T K) * scale : M=N=4096, K=512. Q,K stored [c, n] (k-major).
    {
        dim3 grid(kHW / 128, kHW / 128, kB);  // (32, 32, 4)
        gemm_kernel<1, 0, 1><<<grid, 256>>>(q, k, nullptr, nullptr, sim,
                                            kHW, kHW, kC, sCN, sCN, sNN, scale);
    }

    // 4) softmax over each row of sim
    softmax_kernel<<<kB * kHW, 256>>>(sim);

    // 5) O2[c][q] = sum_k V[c][k] * attn[q][k] : M=512, N=4096, K=4096
    {
        dim3 grid(kHW / 128, kC / 128, kB);  // (32, 4, 4)
        gemm_kernel<0, 1, 1><<<grid, 256>>>(v, sim, nullptr, nullptr, o2,
                                            kC, kHW, kHW, sCN, sNN, sCN, 1.f);
    }

    // 6) out = x + Wo @ O2 + bo : M=512, N=4096, K=512
    {
        dim3 grid(kHW / 128, kC / 128, kB);
        gemm_kernel<0, 0, 2><<<grid, 256>>>(wo, o2, bo, x, out,
                                            kC, kHW, kC, 0, sCN, sCN, 1.f);
    }
}

// round 4
// speedup vs baseline: 2.4223x; 2.4223x over previous
#include <cuda_runtime.h>
#include <cstdint>
#include <math.h>

// ---------------------------------------------------------------------------
// Problem constants
// ---------------------------------------------------------------------------
constexpr int kB  = 4;
constexpr int kC  = 512;
constexpr int kHW = 4096;
constexpr int kG  = 32;
constexpr int kCPG = kC / kG;   // 16
constexpr float kEPS = 1e-6f;

// Scratch (__device__ globals per allocation-free rule)
__device__ float g_hT [(size_t)kB * kHW * kC];   // GN out, transposed [b][n][c] (tf32)
__device__ float g_qt [(size_t)kB * kHW * kC];   // Q^T [b][n][c] (tf32)
__device__ float g_kt [(size_t)kB * kHW * kC];   // K^T [b][n][c] (tf32)
__device__ float g_v  [(size_t)kB * kC * kHW];   // V   [b][c][n] (tf32)
__device__ float g_o2 [(size_t)kB * kHW * kC];   // attn@V [b][n][c] (tf32)
__device__ float g_sim[(size_t)kB * kHW * kHW];  // 256 MB
__device__ float g_aff[(size_t)kB * kC * 2];     // per-channel (scale, offset)
__device__ float g_wr [4 * kC * kC];             // tf32-rounded wq,wk,wv,wo

// ---------------------------------------------------------------------------
// Helpers
// ---------------------------------------------------------------------------
__device__ __forceinline__ float to_tf32(float x) {
    float y;
    asm("cvt.rna.tf32.f32 %0, %1;" : "=f"(y) : "f"(x));
    return y;
}
__device__ __forceinline__ uint32_t smem_u32(const void* p) {
    uint32_t a;
    asm("{ .reg .u64 t; cvta.to.shared.u64 t, %1; cvt.u32.u64 %0, t; }"
        : "=r"(a) : "l"(p));
    return a;
}
__device__ __forceinline__ void cp16(uint32_t dst, const void* src) {
    asm volatile("cp.async.cg.shared.global [%0], [%1], 16;\n"
                 :: "r"(dst), "l"(src));
}
__device__ __forceinline__ void cp_commit() {
    asm volatile("cp.async.commit_group;\n" ::: "memory");
}
__device__ __forceinline__ void cp_wait1() {
    asm volatile("cp.async.wait_group 1;\n" ::: "memory");
}
// m16n8k8 tf32 mma, row.col, fp32 accum
__device__ __forceinline__ void mma8(float* d, const uint32_t* a, const uint32_t* b) {
    asm volatile(
        "mma.sync.aligned.m16n8k8.row.col.f32.tf32.tf32.f32 "
        "{%0,%1,%2,%3}, {%4,%5,%6,%7}, {%8,%9}, {%0,%1,%2,%3};"
        : "+f"(d[0]), "+f"(d[1]), "+f"(d[2]), "+f"(d[3])
        : "r"(a[0]), "r"(a[1]), "r"(a[2]), "r"(a[3]), "r"(b[0]), "r"(b[1]));
}

// ---------------------------------------------------------------------------
// Weight prep: round 4 weight matrices to tf32
// ---------------------------------------------------------------------------
__global__ void prep_weights(const float* __restrict__ wq, const float* __restrict__ wk,
                             const float* __restrict__ wv, const float* __restrict__ wo,
                             float* __restrict__ wr) {
    const int i = blockIdx.x * blockDim.x + threadIdx.x;
    const int n = kC * kC;
    if (i < n) {
        wr[0 * n + i] = to_tf32(wq[i]);
        wr[1 * n + i] = to_tf32(wk[i]);
        wr[2 * n + i] = to_tf32(wv[i]);
        wr[3 * n + i] = to_tf32(wo[i]);
    }
}

// ---------------------------------------------------------------------------
// GroupNorm pass 1: per-(b,g) mean/var -> per-channel affine (a, b)
// ---------------------------------------------------------------------------
__global__ void gn_stats(const float* __restrict__ x,
                         const float* __restrict__ gamma,
                         const float* __restrict__ beta,
                         float* __restrict__ aff) {
    const int b = blockIdx.x / kG, g = blockIdx.x % kG;
    const float* xp = x + ((size_t)b * kC + (size_t)g * kCPG) * kHW;
    const int N = kCPG * kHW;

    float s = 0.f, ss = 0.f;
    for (int i = threadIdx.x; i < N; i += 256) {
        float v = xp[i];
        s += v; ss += v * v;
    }
    __shared__ float sh1[256], sh2[256];
    sh1[threadIdx.x] = s; sh2[threadIdx.x] = ss;
    __syncthreads();
    for (int o = 128; o > 0; o >>= 1) {
        if (threadIdx.x < o) {
            sh1[threadIdx.x] += sh1[threadIdx.x + o];
            sh2[threadIdx.x] += sh2[threadIdx.x + o];
        }
        __syncthreads();
    }
    if (threadIdx.x < kCPG) {
        const float mean = sh1[0] / (float)N;
        const float var  = sh2[0] / (float)N - mean * mean;
        const float rinv = rsqrtf(var + kEPS);
        const int ch = g * kCPG + threadIdx.x;
        const float a = rinv * gamma[ch];
        aff[((size_t)b * kC + ch) * 2 + 0] = a;
        aff[((size_t)b * kC + ch) * 2 + 1] = beta[ch] - mean * a;
    }
}

// ---------------------------------------------------------------------------
// GroupNorm pass 2: normalize + transpose + tf32 round: x[b][c][n] -> hT[b][n][c]
// ---------------------------------------------------------------------------
__global__ void gn_norm_t(const float* __restrict__ x,
                          const float* __restrict__ aff,
                          float* __restrict__ hT) {
    __shared__ float t[32][33];
    const int b = blockIdx.z;
    const int n0 = blockIdx.x * 32, c0 = blockIdx.y * 32;
    const int tx = threadIdx.x, ty = threadIdx.y;   // 32 x 8
    const float* xb = x  + (size_t)b * kC * kHW;
    float*       hb = hT + (size_t)b * kHW * kC;

    #pragma unroll
    for (int r = 0; r < 4; r++) {
        const int c = c0 + ty + r * 8;
        const float a  = aff[((size_t)b * kC + c) * 2 + 0];
        const float bb = aff[((size_t)b * kC + c) * 2 + 1];
        t[ty + r * 8][tx] = to_tf32(xb[(size_t)c * kHW + n0 + tx] * a + bb);
    }
    __syncthreads();
    #pragma unroll
    for (int r = 0; r < 4; r++) {
        const int n = n0 + ty + r * 8;
        hb[(size_t)n * kC + c0 + tx] = t[tx][ty + r * 8];
    }
}

// ---------------------------------------------------------------------------
// tf32 mma.sync GEMM: C[m][n] = sum_k A[m][k] * B[n][k]  (both K-major)
// 128x128x16 tile, 256 threads, 8 warps (2x4), warp tile 64x32.
// Static 40KB smem (fits default limit -> no cudaFuncSetAttribute needed).
// EPI: 0=+bias[n], 1=+bias[m], 2=*alpha, 3=none, 4=+bias[m]+res[m][n]
// CVT: round output to tf32 (for consumption by the next GEMM)
// ---------------------------------------------------------------------------
constexpr int kPad = 20;                 // padded row stride (floats), 16 + 4
constexpr int kTileF = 128 * kPad;       // 2560 floats per tile (A or B)
constexpr int kStageF = 2 * kTileF;      // 5120 floats per stage (A + B)

template <int EPI, int CVT>
__global__ void __launch_bounds__(256, 1)
gemm_mma(const float* __restrict__ A, const float* __restrict__ B,
         const float* __restrict__ bias, const float* __restrict__ res,
         float* __restrict__ C,
         int lda, int ldb, int ldc, int K,
         size_t sA, size_t sB, size_t sC, float alpha) {
    __shared__ float sm[2 * kStageF];    // 40,960 bytes
    const int tid = threadIdx.x;
    const int lane = tid & 31, wid = tid >> 5;
    const int wm = wid & 1, wn = wid >> 1;   // warp grid 2 x 4

    const int bz = blockIdx.z;
    const float* Ab = A + sA * bz;
    const float* Bb = B + sB * bz;
    float*       Cb = C + sC * bz;
    const int m0 = blockIdx.y * 128;
    const int n0 = blockIdx.x * 128;

    const uint32_t smAddr = smem_u32(sm);
    const int KT = K / 16;

    // prefetch one 128x16 A tile + 128x16 B tile into stage p
    auto prefetch = [&](int it, int p) {
        const int k0 = it * 16;
        const uint32_t aBase = smAddr + (uint32_t)(p * kStageF) * 4u;
        const uint32_t bBase = aBase + (uint32_t)kTileF * 4u;
        #pragma unroll
        for (int t = 0; t < 2; t++) {
            const int idx = t * 256 + tid;   // 0..511
            const int row = idx >> 2, c4 = (idx & 3) * 4;
            cp16(aBase + (uint32_t)(row * kPad + c4) * 4u,
                 Ab + (size_t)(m0 + row) * lda + k0 + c4);
            cp16(bBase + (uint32_t)(row * kPad + c4) * 4u,
                 Bb + (size_t)(n0 + row) * ldb + k0 + c4);
        }
    };

    float acc[4][4][4];
    #pragma unroll
    for (int i = 0; i < 4; i++)
        #pragma unroll
        for (int j = 0; j < 4; j++)
            #pragma unroll
            for (int r = 0; r < 4; r++) acc[i][j][r] = 0.f;

    prefetch(0, 0);
    cp_commit();

    const int rA = (lane >> 2);      // 0..7
    const int cA = (lane & 3);       // 0..3

    for (int it = 0; it < KT; ++it) {
        const int p = it & 1;
        if (it + 1 < KT) prefetch(it + 1, p ^ 1);
        cp_commit();
        cp_wait1();
        __syncthreads();

        const float* As = sm + p * kStageF;
        const float* Bs = As + kTileF;

        #pragma unroll
        for (int kk = 0; kk < 2; kk++) {
            const int c = kk * 8 + cA;
            uint32_t af[4][4];
            #pragma unroll
            for (int mt = 0; mt < 4; mt++) {
                const int r = wm * 64 + mt * 16 + rA;
                af[mt][0] = __float_as_uint(As[r * kPad + c]);
                af[mt][1] = __float_as_uint(As[(r + 8) * kPad + c]);
                af[mt][2] = __float_as_uint(As[r * kPad + c + 4]);
                af[mt][3] = __float_as_uint(As[(r + 8) * kPad + c + 4]);
            }
            uint32_t bf[4][2];
            #pragma unroll
            for (int nt = 0; nt < 4; nt++) {
                const int n = wn * 32 + nt * 8 + rA;
                bf[nt][0] = __float_as_uint(Bs[n * kPad + c]);
                bf[nt][1] = __float_as_uint(Bs[n * kPad + c + 4]);
            }
            #pragma unroll
            for (int mt = 0; mt < 4; mt++)
                #pragma unroll
                for (int nt = 0; nt < 4; nt++)
                    mma8(acc[mt][nt], af[mt], bf[nt]);
        }
        __syncthreads();
    }

    // ---- epilogue ----
    #pragma unroll
    for (int mt = 0; mt < 4; mt++) {
        const int r0 = m0 + wm * 64 + mt * 16 + rA;
        float bm0 = 0.f, bm1 = 0.f;
        if (EPI == 1 || EPI == 4) { bm0 = bias[r0]; bm1 = bias[r0 + 8]; }
        #pragma unroll
        for (int nt = 0; nt < 4; nt++) {
            const int col = n0 + wn * 32 + nt * 8 + cA * 2;
            float d0 = acc[mt][nt][0], d1 = acc[mt][nt][1];
            float d2 = acc[mt][nt][2], d3 = acc[mt][nt][3];
            if (EPI == 0) {
                const float b0 = bias[col], b1 = bias[col + 1];
                d0 += b0; d1 += b1; d2 += b0; d3 += b1;
            } else if (EPI == 1 || EPI == 4) {
                d0 += bm0; d1 += bm0; d2 += bm1; d3 += bm1;
            } else if (EPI == 2) {
                d0 *= alpha; d1 *= alpha; d2 *= alpha; d3 *= alpha;
            }
            if (EPI == 4) {
                const float* rp = res + sC * bz;
                d0 += rp[(size_t)r0 * ldc + col];
                d1 += rp[(size_t)r0 * ldc + col + 1];
                d2 += rp[(size_t)(r0 + 8) * ldc + col];
                d3 += rp[(size_t)(r0 + 8) * ldc + col + 1];
            }
            if (CVT) {
                d0 = to_tf32(d0); d1 = to_tf32(d1);
                d2 = to_tf32(d2); d3 = to_tf32(d3);
            }
            *(float2*)(Cb + (size_t)r0 * ldc + col)       = make_float2(d0, d1);
            *(float2*)(Cb + (size_t)(r0 + 8) * ldc + col) = make_float2(d2, d3);
        }
    }
}

// ---------------------------------------------------------------------------
// Row softmax over 4096 elems, one block (256 thr) per row, in-place, tf32 out.
// ---------------------------------------------------------------------------
__global__ void softmax_kernel(float* __restrict__ sim) {
    float* p = sim + (size_t)blockIdx.x * kHW;
    const int tid = threadIdx.x;
    float v[16];
    float mx = -1e30f;
    #pragma unroll
    for (int i = 0; i < 16; i++) {
        v[i] = p[tid + i * 256];
        mx = fmaxf(mx, v[i]);
    }
    __shared__ float sh[256];
    sh[tid] = mx; __syncthreads();
    for (int o = 128; o > 0; o >>= 1) {
        if (tid < o) sh[tid] = fmaxf(sh[tid], sh[tid + o]);
        __syncthreads();
    }
    mx = sh[0];
    __syncthreads();
    float s = 0.f;
    #pragma unroll
    for (int i = 0; i < 16; i++) { v[i] = __expf(v[i] - mx); s += v[i]; }
    sh[tid] = s; __syncthreads();
    for (int o = 128; o > 0; o >>= 1) {
        if (tid < o) sh[tid] += sh[tid + o];
        __syncthreads();
    }
    const float rinv = 1.f / sh[0];
    #pragma unroll
    for (int i = 0; i < 16; i++) p[tid + i * 256] = to_tf32(v[i] * rinv);
}

// ---------------------------------------------------------------------------
extern "C" void kernel_launch(void* const* d_in, const int* in_sizes, int n_in,
                              void* d_out, int out_size) {
    const float* x     = (const float*)d_in[0];
    const float* gamma = (const float*)d_in[1];
    const float* beta  = (const float*)d_in[2];
    const float* wq    = (const float*)d_in[3];
    const float* bq    = (const float*)d_in[4];
    const float* wk    = (const float*)d_in[5];
    const float* bk    = (const float*)d_in[6];
    const float* wv    = (const float*)d_in[7];
    const float* bv    = (const float*)d_in[8];
    const float* wo    = (const float*)d_in[9];
    const float* bo    = (const float*)d_in[10];
    float* out = (float*)d_out;

    float *hT, *qt, *kt, *v, *o2, *sim, *aff, *wr;
    cudaGetSymbolAddress((void**)&hT,  g_hT);
    cudaGetSymbolAddress((void**)&qt,  g_qt);
    cudaGetSymbolAddress((void**)&kt,  g_kt);
    cudaGetSymbolAddress((void**)&v,   g_v);
    cudaGetSymbolAddress((void**)&o2,  g_o2);
    cudaGetSymbolAddress((void**)&sim, g_sim);
    cudaGetSymbolAddress((void**)&aff, g_aff);
    cudaGetSymbolAddress((void**)&wr,  g_wr);

    const size_t sNC = (size_t)kHW * kC;    // per-batch [n][c] / [c][n]
    const size_t sNN = (size_t)kHW * kHW;   // per-batch sim
    const float  scale = 1.0f / sqrtf((float)kC);
    const int nW = kC * kC;

    // 0) round weights to tf32
    prep_weights<<<(nW + 255) / 256, 256>>>(wq, wk, wv, wo, wr);

    // 1) GroupNorm (stats + fused normalize-transpose-round)
    gn_stats<<<kB * kG, 256>>>(x, gamma, beta, aff);
    gn_norm_t<<<dim3(kHW / 32, kC / 32, kB), dim3(32, 8)>>>(x, aff, hT);

    // 2) Qt / Kt = hT @ W^T  (M=4096, N=512, K=512), bias over columns
    {
        dim3 grid(kC / 128, kHW / 128, kB);
        gemm_mma<0,1><<<grid, 256>>>(hT, wr + 0 * nW, bq, nullptr, qt,
                                     kC, kC, kC, kC, sNC, 0, sNC, 1.f);
        gemm_mma<0,1><<<grid, 256>>>(hT, wr + 1 * nW, bk, nullptr, kt,
                                     kC, kC, kC, kC, sNC, 0, sNC, 1.f);
    }
    // 3) V = Wv @ H  (M=512, N=4096, K=512), output [c][n], bias over rows
    {
        dim3 grid(kHW / 128, kC / 128, kB);
        gemm_mma<1,1><<<grid, 256>>>(wr + 2 * nW, hT, bv, nullptr, v,
                                     kC, kC, kHW, kC, 0, sNC, sNC, 1.f);
    }
    // 4) sim = Qt @ Kt^T * scale  (M=N=4096, K=512)
    {
        dim3 grid(kHW / 128, kHW / 128, kB);
        gemm_mma<2,0><<<grid, 256>>>(qt, kt, nullptr, nullptr, sim,
                                     kC, kC, kHW, kC, sNC, sNC, sNN, scale);
    }
    // 5) softmax rows (tf32-rounded output)
    softmax_kernel<<<kB * kHW, 256>>>(sim);

    // 6) o2 = attn @ V^T  (M=4096, N=512, K=4096), output [n][c]
    {
        dim3 grid(kC / 128, kHW / 128, kB);
        gemm_mma<3,1><<<grid, 256>>>(sim, v, nullptr, nullptr, o2,
                                     kHW, kHW, kC, kHW, sNN, sNC, sNC, 1.f);
    }
    // 7) out = x + Wo @ o2^T + bo  (M=512, N=4096, K=512), output [c][n]
    {
        dim3 grid(kHW / 128, kC / 128, kB);
        gemm_mma<4,0><<<grid, 256>>>(wr + 3 * nW, o2, bo, x, out,
                                     kC, kC, kHW, kC, 0, sNC, sNC, 1.f);
    }
}

// round 5
// speedup vs baseline: 4.3492x; 1.7955x over previous
#include <cuda_runtime.h>
#include <cuda_bf16.h>
#include <cstdint>
#include <math.h>

// ---------------------------------------------------------------------------
// Problem constants
// ---------------------------------------------------------------------------
constexpr int kB  = 4;
constexpr int kC  = 512;
constexpr int kHW = 4096;
constexpr int kG  = 32;
constexpr int kCPG = kC / kG;   // 16
constexpr float kEPS = 1e-6f;

// Scratch (__device__ globals per allocation-free rule)
__device__ __nv_bfloat16 g_hT [(size_t)kB * kHW * kC];   // GN out [b][n][c]
__device__ __nv_bfloat16 g_qt [(size_t)kB * kHW * kC];   // Q^T [b][n][c]
__device__ __nv_bfloat16 g_kt [(size_t)kB * kHW * kC];   // K^T [b][n][c]
__device__ __nv_bfloat16 g_v  [(size_t)kB * kC * kHW];   // V   [b][c][n]
__device__ __nv_bfloat16 g_o2 [(size_t)kB * kHW * kC];   // attn@V [b][n][c]
__device__ float         g_sim [(size_t)kB * kHW * kHW]; // logits f32 (256 MB)
__device__ __nv_bfloat16 g_simh[(size_t)kB * kHW * kHW]; // attn bf16 (128 MB)
__device__ float         g_aff[(size_t)kB * kC * 2];     // (scale, offset)
__device__ __nv_bfloat16 g_wh [4 * kC * kC];             // bf16 wq,wk,wv,wo

// ---------------------------------------------------------------------------
// Helpers
// ---------------------------------------------------------------------------
__device__ __forceinline__ uint32_t smem_u32(const void* p) {
    uint32_t a;
    asm("{ .reg .u64 t; cvta.to.shared.u64 t, %1; cvt.u32.u64 %0, t; }"
        : "=r"(a) : "l"(p));
    return a;
}
__device__ __forceinline__ void cp16(uint32_t dst, const void* src) {
    asm volatile("cp.async.cg.shared.global [%0], [%1], 16;\n"
                 :: "r"(dst), "l"(src));
}
__device__ __forceinline__ void cp_commit() {
    asm volatile("cp.async.commit_group;\n" ::: "memory");
}
__device__ __forceinline__ void cp_wait1() {
    asm volatile("cp.async.wait_group 1;\n" ::: "memory");
}
// m16n8k16 bf16 mma, row.col, fp32 accum
__device__ __forceinline__ void mma16(float* d, const uint32_t* a, const uint32_t* b) {
    asm volatile(
        "mma.sync.aligned.m16n8k16.row.col.f32.bf16.bf16.f32 "
        "{%0,%1,%2,%3}, {%4,%5,%6,%7}, {%8,%9}, {%0,%1,%2,%3};"
        : "+f"(d[0]), "+f"(d[1]), "+f"(d[2]), "+f"(d[3])
        : "r"(a[0]), "r"(a[1]), "r"(a[2]), "r"(a[3]), "r"(b[0]), "r"(b[1]));
}

// ---------------------------------------------------------------------------
// Weight prep: round 4 weight matrices to bf16
// ---------------------------------------------------------------------------
__global__ void prep_weights(const float* __restrict__ wq, const float* __restrict__ wk,
                             const float* __restrict__ wv, const float* __restrict__ wo,
                             __nv_bfloat16* __restrict__ wh) {
    const int i = blockIdx.x * blockDim.x + threadIdx.x;
    const int n = kC * kC;
    if (i < n) {
        wh[0 * n + i] = __float2bfloat16_rn(wq[i]);
        wh[1 * n + i] = __float2bfloat16_rn(wk[i]);
        wh[2 * n + i] = __float2bfloat16_rn(wv[i]);
        wh[3 * n + i] = __float2bfloat16_rn(wo[i]);
    }
}

// ---------------------------------------------------------------------------
// GroupNorm pass 1: per-(b,g) mean/var -> per-channel affine (a, b)
// ---------------------------------------------------------------------------
__global__ void gn_stats(const float* __restrict__ x,
                         const float* __restrict__ gamma,
                         const float* __restrict__ beta,
                         float* __restrict__ aff) {
    const int b = blockIdx.x / kG, g = blockIdx.x % kG;
    const float* xp = x + ((size_t)b * kC + (size_t)g * kCPG) * kHW;
    const int N = kCPG * kHW;

    float s = 0.f, ss = 0.f;
    for (int i = threadIdx.x; i < N; i += 256) {
        float v = xp[i];
        s += v; ss += v * v;
    }
    __shared__ float sh1[256], sh2[256];
    sh1[threadIdx.x] = s; sh2[threadIdx.x] = ss;
    __syncthreads();
    for (int o = 128; o > 0; o >>= 1) {
        if (threadIdx.x < o) {
            sh1[threadIdx.x] += sh1[threadIdx.x + o];
            sh2[threadIdx.x] += sh2[threadIdx.x + o];
        }
        __syncthreads();
    }
    if (threadIdx.x < kCPG) {
        const float mean = sh1[0] / (float)N;
        const float var  = sh2[0] / (float)N - mean * mean;
        const float rinv = rsqrtf(var + kEPS);
        const int ch = g * kCPG + threadIdx.x;
        const float a = rinv * gamma[ch];
        aff[((size_t)b * kC + ch) * 2 + 0] = a;
        aff[((size_t)b * kC + ch) * 2 + 1] = beta[ch] - mean * a;
    }
}

// ---------------------------------------------------------------------------
// GroupNorm pass 2: normalize + transpose + bf16: x[b][c][n] -> hT[b][n][c]
// ---------------------------------------------------------------------------
__global__ void gn_norm_t(const float* __restrict__ x,
                          const float* __restrict__ aff,
                          __nv_bfloat16* __restrict__ hT) {
    __shared__ float t[32][33];
    const int b = blockIdx.z;
    const int n0 = blockIdx.x * 32, c0 = blockIdx.y * 32;
    const int tx = threadIdx.x, ty = threadIdx.y;   // 32 x 8
    const float* xb = x  + (size_t)b * kC * kHW;
    __nv_bfloat16* hb = hT + (size_t)b * kHW * kC;

    #pragma unroll
    for (int r = 0; r < 4; r++) {
        const int c = c0 + ty + r * 8;
        const float a  = aff[((size_t)b * kC + c) * 2 + 0];
        const float bb = aff[((size_t)b * kC + c) * 2 + 1];
        t[ty + r * 8][tx] = xb[(size_t)c * kHW + n0 + tx] * a + bb;
    }
    __syncthreads();
    #pragma unroll
    for (int r = 0; r < 4; r++) {
        const int n = n0 + ty + r * 8;
        hb[(size_t)n * kC + c0 + tx] = __float2bfloat16_rn(t[tx][ty + r * 8]);
    }
}

// ---------------------------------------------------------------------------
// bf16 mma.sync GEMM: C[m][n] = sum_k A[m][k] * B[n][k]  (both K-major bf16)
// 128x128x32 tile, 256 threads, 8 warps (2x4), warp tile 64x32.
// smem per tile row: 16 words data + 4 pad = 20 words (conflict-free).
// EPI: 0=+bias[n]->bf16, 1=+bias[m]->bf16, 2=*alpha->f32, 3=none->bf16,
//      4=+bias[m]+res[m][n]->f32
// ---------------------------------------------------------------------------
constexpr int kWpad   = 20;              // padded row stride (32-bit words)
constexpr int kTileW  = 128 * kWpad;     // 2560 words per tile (A or B)
constexpr int kStageW = 2 * kTileW;      // 5120 words per stage (A + B)

template <int EPI>
__global__ void __launch_bounds__(256, 1)
gemm_bf16(const __nv_bfloat16* __restrict__ A, const __nv_bfloat16* __restrict__ B,
          const float* __restrict__ bias, const float* __restrict__ res,
          void* __restrict__ Cv,
          int lda, int ldb, int ldc, int K,
          size_t sA, size_t sB, size_t sC, float alpha) {
    __shared__ __align__(16) uint32_t sm[2 * kStageW];   // 40,960 bytes
    const int tid = threadIdx.x;
    const int lane = tid & 31, wid = tid >> 5;
    const int wm = wid & 1, wn = wid >> 1;   // warp grid 2 x 4

    const int bz = blockIdx.z;
    const __nv_bfloat16* Ab = A + sA * bz;
    const __nv_bfloat16* Bb = B + sB * bz;
    const int m0 = blockIdx.y * 128;
    const int n0 = blockIdx.x * 128;

    const uint32_t smAddr = smem_u32(sm);
    const int KT = K / 32;

    // prefetch one 128x32(bf16) A tile + B tile into stage p
    auto prefetch = [&](int it, int p) {
        const int k0 = it * 32;
        const uint32_t aBase = smAddr + (uint32_t)(p * kStageW) * 4u;
        const uint32_t bBase = aBase + (uint32_t)kTileW * 4u;
        #pragma unroll
        for (int t = 0; t < 2; t++) {
            const int idx = t * 256 + tid;   // 0..511
            const int row = idx >> 2, seg = idx & 3;     // seg: 16B = 8 bf16
            const uint32_t so = (uint32_t)(row * kWpad + seg * 4) * 4u;
            cp16(aBase + so, Ab + (size_t)(m0 + row) * lda + k0 + seg * 8);
            cp16(bBase + so, Bb + (size_t)(n0 + row) * ldb + k0 + seg * 8);
        }
    };

    float acc[4][4][4];
    #pragma unroll
    for (int i = 0; i < 4; i++)
        #pragma unroll
        for (int j = 0; j < 4; j++)
            #pragma unroll
            for (int r = 0; r < 4; r++) acc[i][j][r] = 0.f;

    prefetch(0, 0);
    cp_commit();

    const int rA = (lane >> 2);      // 0..7
    const int cA = (lane & 3);       // 0..3

    for (int it = 0; it < KT; ++it) {
        const int p = it & 1;
        if (it + 1 < KT) prefetch(it + 1, p ^ 1);
        cp_commit();
        cp_wait1();
        __syncthreads();

        const uint32_t* As = sm + p * kStageW;
        const uint32_t* Bs = As + kTileW;

        #pragma unroll
        for (int kk = 0; kk < 2; kk++) {          // two k16 steps
            const int w = kk * 8 + cA;            // k-word index
            uint32_t af[4][4];
            #pragma unroll
            for (int mt = 0; mt < 4; mt++) {
                const int r = wm * 64 + mt * 16 + rA;
                af[mt][0] = As[r * kWpad + w];
                af[mt][1] = As[(r + 8) * kWpad + w];
                af[mt][2] = As[r * kWpad + w + 4];
                af[mt][3] = As[(r + 8) * kWpad + w + 4];
            }
            uint32_t bf[4][2];
            #pragma unroll
            for (int nt = 0; nt < 4; nt++) {
                const int n = wn * 32 + nt * 8 + rA;
                bf[nt][0] = Bs[n * kWpad + w];
                bf[nt][1] = Bs[n * kWpad + w + 4];
            }
            #pragma unroll
            for (int mt = 0; mt < 4; mt++)
                #pragma unroll
                for (int nt = 0; nt < 4; nt++)
                    mma16(acc[mt][nt], af[mt], bf[nt]);
        }
        __syncthreads();
    }

    // ---- epilogue ----
    constexpr bool OUTB = (EPI == 0 || EPI == 1 || EPI == 3);
    #pragma unroll
    for (int mt = 0; mt < 4; mt++) {
        const int r0 = m0 + wm * 64 + mt * 16 + rA;
        float bm0 = 0.f, bm1 = 0.f;
        if (EPI == 1 || EPI == 4) { bm0 = bias[r0]; bm1 = bias[r0 + 8]; }
        #pragma unroll
        for (int nt = 0; nt < 4; nt++) {
            const int col = n0 + wn * 32 + nt * 8 + cA * 2;
            float d0 = acc[mt][nt][0], d1 = acc[mt][nt][1];
            float d2 = acc[mt][nt][2], d3 = acc[mt][nt][3];
            if (EPI == 0) {
                const float b0 = bias[col], b1 = bias[col + 1];
                d0 += b0; d1 += b1; d2 += b0; d3 += b1;
            } else if (EPI == 1 || EPI == 4) {
                d0 += bm0; d1 += bm0; d2 += bm1; d3 += bm1;
            } else if (EPI == 2) {
                d0 *= alpha; d1 *= alpha; d2 *= alpha; d3 *= alpha;
            }
            if (EPI == 4) {
                const float* rp = res + sC * bz;
                d0 += rp[(size_t)r0 * ldc + col];
                d1 += rp[(size_t)r0 * ldc + col + 1];
                d2 += rp[(size_t)(r0 + 8) * ldc + col];
                d3 += rp[(size_t)(r0 + 8) * ldc + col + 1];
            }
            if (OUTB) {
                __nv_bfloat16* Cb = (__nv_bfloat16*)Cv + sC * bz;
                *(__nv_bfloat162*)(Cb + (size_t)r0 * ldc + col) =
                    __floats2bfloat162_rn(d0, d1);
                *(__nv_bfloat162*)(Cb + (size_t)(r0 + 8) * ldc + col) =
                    __floats2bfloat162_rn(d2, d3);
            } else {
                float* Cb = (float*)Cv + sC * bz;
                *(float2*)(Cb + (size_t)r0 * ldc + col)       = make_float2(d0, d1);
                *(float2*)(Cb + (size_t)(r0 + 8) * ldc + col) = make_float2(d2, d3);
            }
        }
    }
}

// ---------------------------------------------------------------------------
// Row softmax over 4096 f32 logits -> bf16 attn; one block (256 thr) per row.
// ---------------------------------------------------------------------------
__global__ void softmax_kernel(const float* __restrict__ sim,
                               __nv_bfloat16* __restrict__ simh) {
    const float* p = sim + (size_t)blockIdx.x * kHW;
    __nv_bfloat16* ph = simh + (size_t)blockIdx.x * kHW;
    const int tid = threadIdx.x;
    float v[16];
    float mx = -1e30f;
    #pragma unroll
    for (int i = 0; i < 16; i++) {
        v[i] = p[tid + i * 256];
        mx = fmaxf(mx, v[i]);
    }
    __shared__ float sh[256];
    sh[tid] = mx; __syncthreads();
    for (int o = 128; o > 0; o >>= 1) {
        if (tid < o) sh[tid] = fmaxf(sh[tid], sh[tid + o]);
        __syncthreads();
    }
    mx = sh[0];
    __syncthreads();
    float s = 0.f;
    #pragma unroll
    for (int i = 0; i < 16; i++) { v[i] = __expf(v[i] - mx); s += v[i]; }
    sh[tid] = s; __syncthreads();
    for (int o = 128; o > 0; o >>= 1) {
        if (tid < o) sh[tid] += sh[tid + o];
        __syncthreads();
    }
    const float rinv = 1.f / sh[0];
    #pragma unroll
    for (int i = 0; i < 16; i++)
        ph[tid + i * 256] = __float2bfloat16_rn(v[i] * rinv);
}

// ---------------------------------------------------------------------------
extern "C" void kernel_launch(void* const* d_in, const int* in_sizes, int n_in,
                              void* d_out, int out_size) {
    const float* x     = (const float*)d_in[0];
    const float* gamma = (const float*)d_in[1];
    const float* beta  = (const float*)d_in[2];
    const float* wq    = (const float*)d_in[3];
    const float* bq    = (const float*)d_in[4];
    const float* wk    = (const float*)d_in[5];
    const float* bk    = (const float*)d_in[6];
    const float* wv    = (const float*)d_in[7];
    const float* bv    = (const float*)d_in[8];
    const float* wo    = (const float*)d_in[9];
    const float* bo    = (const float*)d_in[10];
    float* out = (float*)d_out;

    __nv_bfloat16 *hT, *qt, *kt, *v, *o2, *simh, *wh;
    float *sim, *aff;
    cudaGetSymbolAddress((void**)&hT,   g_hT);
    cudaGetSymbolAddress((void**)&qt,   g_qt);
    cudaGetSymbolAddress((void**)&kt,   g_kt);
    cudaGetSymbolAddress((void**)&v,    g_v);
    cudaGetSymbolAddress((void**)&o2,   g_o2);
    cudaGetSymbolAddress((void**)&sim,  g_sim);
    cudaGetSymbolAddress((void**)&simh, g_simh);
    cudaGetSymbolAddress((void**)&aff,  g_aff);
    cudaGetSymbolAddress((void**)&wh,   g_wh);

    const size_t sNC = (size_t)kHW * kC;    // per-batch [n][c] / [c][n]
    const size_t sNN = (size_t)kHW * kHW;   // per-batch sim
    const float  scale = 1.0f / sqrtf((float)kC);
    const int nW = kC * kC;

    // 0) weights -> bf16
    prep_weights<<<(nW + 255) / 256, 256>>>(wq, wk, wv, wo, wh);

    // 1) GroupNorm (stats + fused normalize-transpose-bf16)
    gn_stats<<<kB * kG, 256>>>(x, gamma, beta, aff);
    gn_norm_t<<<dim3(kHW / 32, kC / 32, kB), dim3(32, 8)>>>(x, aff, hT);

    // 2) Qt / Kt = hT @ W^T  (M=4096, N=512, K=512), bias over columns
    {
        dim3 grid(kC / 128, kHW / 128, kB);
        gemm_bf16<0><<<grid, 256>>>(hT, wh + 0 * nW, bq, nullptr, qt,
                                    kC, kC, kC, kC, sNC, 0, sNC, 1.f);
        gemm_bf16<0><<<grid, 256>>>(hT, wh + 1 * nW, bk, nullptr, kt,
                                    kC, kC, kC, kC, sNC, 0, sNC, 1.f);
    }
    // 3) V = Wv @ H  (M=512, N=4096, K=512), output [c][n], bias over rows
    {
        dim3 grid(kHW / 128, kC / 128, kB);
        gemm_bf16<1><<<grid, 256>>>(wh + 2 * nW, hT, bv, nullptr, v,
                                    kC, kC, kHW, kC, 0, sNC, sNC, 1.f);
    }
    // 4) sim = Qt @ Kt^T * scale  (M=N=4096, K=512), f32 out
    {
        dim3 grid(kHW / 128, kHW / 128, kB);
        gemm_bf16<2><<<grid, 256>>>(qt, kt, nullptr, nullptr, sim,
                                    kC, kC, kHW, kC, sNC, sNC, sNN, scale);
    }
    // 5) softmax rows -> bf16
    softmax_kernel<<<kB * kHW, 256>>>(sim, simh);

    // 6) o2 = attn @ V^T  (M=4096, N=512, K=4096), output [n][c] bf16
    {
        dim3 grid(kC / 128, kHW / 128, kB);
        gemm_bf16<3><<<grid, 256>>>(simh, v, nullptr, nullptr, o2,
                                    kHW, kHW, kC, kHW, sNN, sNC, sNC, 1.f);
    }
    // 7) out = x + Wo @ o2^T + bo  (M=512, N=4096, K=512), f32 out
    {
        dim3 grid(kHW / 128, kC / 128, kB);
        gemm_bf16<4><<<grid, 256>>>(wh + 3 * nW, o2, bo, x, out,
                                    kC, kC, kHW, kC, 0, sNC, sNC, 1.f);
    }
}

// round 6
// speedup vs baseline: 5.1355x; 1.1808x over previous
#include <cuda_runtime.h>
#include <cuda_bf16.h>
#include <cstdint>
#include <math.h>

// ---------------------------------------------------------------------------
// Problem constants
// ---------------------------------------------------------------------------
constexpr int kB  = 4;
constexpr int kC  = 512;
constexpr int kHW = 4096;
constexpr int kG  = 32;
constexpr int kCPG = kC / kG;   // 16
constexpr float kEPS = 1e-6f;

// Scratch (__device__ globals per allocation-free rule)
__device__ __nv_bfloat16 g_hT [(size_t)kB * kHW * kC];   // GN out [b][n][c]
__device__ __nv_bfloat16 g_qt [(size_t)kB * kHW * kC];   // Q^T [b][n][c]
__device__ __nv_bfloat16 g_kt [(size_t)kB * kHW * kC];   // K^T [b][n][c]
__device__ __nv_bfloat16 g_v  [(size_t)kB * kC * kHW];   // V   [b][c][n]
__device__ __nv_bfloat16 g_o2 [(size_t)kB * kHW * kC];   // attn@V [b][n][c]
__device__ float         g_sim [(size_t)kB * kHW * kHW]; // logits f32 (256 MB)
__device__ __nv_bfloat16 g_simh[(size_t)kB * kHW * kHW]; // attn bf16 (128 MB)
__device__ float         g_aff[(size_t)kB * kC * 2];     // (scale, offset)
__device__ __nv_bfloat16 g_wh [4 * kC * kC];             // bf16 wq,wk,wv,wo

// ---------------------------------------------------------------------------
// Helpers
// ---------------------------------------------------------------------------
__device__ __forceinline__ uint32_t smem_u32(const void* p) {
    uint32_t a;
    asm("{ .reg .u64 t; cvta.to.shared.u64 t, %1; cvt.u32.u64 %0, t; }"
        : "=r"(a) : "l"(p));
    return a;
}
__device__ __forceinline__ void cp16(uint32_t dst, const void* src) {
    asm volatile("cp.async.cg.shared.global [%0], [%1], 16;\n"
                 :: "r"(dst), "l"(src));
}
__device__ __forceinline__ void cp_commit() {
    asm volatile("cp.async.commit_group;\n" ::: "memory");
}
__device__ __forceinline__ void cp_wait1() {
    asm volatile("cp.async.wait_group 1;\n" ::: "memory");
}
// m16n8k16 bf16 mma, row.col, fp32 accum
__device__ __forceinline__ void mma16(float* d, const uint32_t* a, const uint32_t* b) {
    asm volatile(
        "mma.sync.aligned.m16n8k16.row.col.f32.bf16.bf16.f32 "
        "{%0,%1,%2,%3}, {%4,%5,%6,%7}, {%8,%9}, {%0,%1,%2,%3};"
        : "+f"(d[0]), "+f"(d[1]), "+f"(d[2]), "+f"(d[3])
        : "r"(a[0]), "r"(a[1]), "r"(a[2]), "r"(a[3]), "r"(b[0]), "r"(b[1]));
}

// ---------------------------------------------------------------------------
// Weight prep: round 4 weight matrices to bf16
// ---------------------------------------------------------------------------
__global__ void prep_weights(const float* __restrict__ wq, const float* __restrict__ wk,
                             const float* __restrict__ wv, const float* __restrict__ wo,
                             __nv_bfloat16* __restrict__ wh) {
    const int i = blockIdx.x * blockDim.x + threadIdx.x;
    const int n = kC * kC;
    if (i < n) {
        wh[0 * n + i] = __float2bfloat16_rn(wq[i]);
        wh[1 * n + i] = __float2bfloat16_rn(wk[i]);
        wh[2 * n + i] = __float2bfloat16_rn(wv[i]);
        wh[3 * n + i] = __float2bfloat16_rn(wo[i]);
    }
}

// ---------------------------------------------------------------------------
// GroupNorm pass 1: per-(b,g) mean/var -> per-channel affine (a, b)
// ---------------------------------------------------------------------------
__global__ void gn_stats(const float* __restrict__ x,
                         const float* __restrict__ gamma,
                         const float* __restrict__ beta,
                         float* __restrict__ aff) {
    const int b = blockIdx.x / kG, g = blockIdx.x % kG;
    const float* xp = x + ((size_t)b * kC + (size_t)g * kCPG) * kHW;
    const int N = kCPG * kHW;

    float s = 0.f, ss = 0.f;
    for (int i = threadIdx.x; i < N; i += 256) {
        float v = xp[i];
        s += v; ss += v * v;
    }
    __shared__ float sh1[256], sh2[256];
    sh1[threadIdx.x] = s; sh2[threadIdx.x] = ss;
    __syncthreads();
    for (int o = 128; o > 0; o >>= 1) {
        if (threadIdx.x < o) {
            sh1[threadIdx.x] += sh1[threadIdx.x + o];
            sh2[threadIdx.x] += sh2[threadIdx.x + o];
        }
        __syncthreads();
    }
    if (threadIdx.x < kCPG) {
        const float mean = sh1[0] / (float)N;
        const float var  = sh2[0] / (float)N - mean * mean;
        const float rinv = rsqrtf(var + kEPS);
        const int ch = g * kCPG + threadIdx.x;
        const float a = rinv * gamma[ch];
        aff[((size_t)b * kC + ch) * 2 + 0] = a;
        aff[((size_t)b * kC + ch) * 2 + 1] = beta[ch] - mean * a;
    }
}

// ---------------------------------------------------------------------------
// GroupNorm pass 2: normalize + transpose + bf16: x[b][c][n] -> hT[b][n][c]
// ---------------------------------------------------------------------------
__global__ void gn_norm_t(const float* __restrict__ x,
                          const float* __restrict__ aff,
                          __nv_bfloat16* __restrict__ hT) {
    __shared__ float t[32][33];
    const int b = blockIdx.z;
    const int n0 = blockIdx.x * 32, c0 = blockIdx.y * 32;
    const int tx = threadIdx.x, ty = threadIdx.y;   // 32 x 8
    const float* xb = x  + (size_t)b * kC * kHW;
    __nv_bfloat16* hb = hT + (size_t)b * kHW * kC;

    #pragma unroll
    for (int r = 0; r < 4; r++) {
        const int c = c0 + ty + r * 8;
        const float a  = aff[((size_t)b * kC + c) * 2 + 0];
        const float bb = aff[((size_t)b * kC + c) * 2 + 1];
        t[ty + r * 8][tx] = xb[(size_t)c * kHW + n0 + tx] * a + bb;
    }
    __syncthreads();
    #pragma unroll
    for (int r = 0; r < 4; r++) {
        const int n = n0 + ty + r * 8;
        hb[(size_t)n * kC + c0 + tx] = __float2bfloat16_rn(t[tx][ty + r * 8]);
    }
}

// ---------------------------------------------------------------------------
// bf16 mma.sync GEMM: C[m][n] = sum_k A[m][k] * B[n][k]  (both K-major bf16)
// 128x128x32 tile, 256 threads, 8 warps (2x4), warp tile 64x32.
// __launch_bounds__(256, 2): 2 CTAs/SM (regs capped at 128) for latency hiding.
// EPI: 0=+bias[n]->bf16, 1=+bias[m]->bf16, 2=*alpha->f32, 3=none->bf16,
//      4=+bias[m]+res[m][n]->f32
// ---------------------------------------------------------------------------
constexpr int kWpad   = 20;              // padded row stride (32-bit words)
constexpr int kTileW  = 128 * kWpad;     // 2560 words per tile (A or B)
constexpr int kStageW = 2 * kTileW;      // 5120 words per stage (A + B)

template <int EPI>
__global__ void __launch_bounds__(256, 2)
gemm_bf16(const __nv_bfloat16* __restrict__ A, const __nv_bfloat16* __restrict__ B,
          const float* __restrict__ bias, const float* __restrict__ res,
          void* __restrict__ Cv,
          int lda, int ldb, int ldc, int K,
          size_t sA, size_t sB, size_t sC, float alpha) {
    __shared__ __align__(16) uint32_t sm[2 * kStageW];   // 40,960 bytes
    const int tid = threadIdx.x;
    const int lane = tid & 31, wid = tid >> 5;
    const int wm = wid & 1, wn = wid >> 1;   // warp grid 2 x 4

    const int bz = blockIdx.z;
    const __nv_bfloat16* Ab = A + sA * bz;
    const __nv_bfloat16* Bb = B + sB * bz;
    const int m0 = blockIdx.y * 128;
    const int n0 = blockIdx.x * 128;

    const uint32_t smAddr = smem_u32(sm);
    const int KT = K / 32;

    // prefetch one 128x32(bf16) A tile + B tile into stage p
    auto prefetch = [&](int it, int p) {
        const int k0 = it * 32;
        const uint32_t aBase = smAddr + (uint32_t)(p * kStageW) * 4u;
        const uint32_t bBase = aBase + (uint32_t)kTileW * 4u;
        #pragma unroll
        for (int t = 0; t < 2; t++) {
            const int idx = t * 256 + tid;   // 0..511
            const int row = idx >> 2, seg = idx & 3;     // seg: 16B = 8 bf16
            const uint32_t so = (uint32_t)(row * kWpad + seg * 4) * 4u;
            cp16(aBase + so, Ab + (size_t)(m0 + row) * lda + k0 + seg * 8);
            cp16(bBase + so, Bb + (size_t)(n0 + row) * ldb + k0 + seg * 8);
        }
    };

    float acc[4][4][4];
    #pragma unroll
    for (int i = 0; i < 4; i++)
        #pragma unroll
        for (int j = 0; j < 4; j++)
            #pragma unroll
            for (int r = 0; r < 4; r++) acc[i][j][r] = 0.f;

    prefetch(0, 0);
    cp_commit();

    const int rA = (lane >> 2);      // 0..7
    const int cA = (lane & 3);       // 0..3

    for (int it = 0; it < KT; ++it) {
        const int p = it & 1;
        if (it + 1 < KT) prefetch(it + 1, p ^ 1);
        cp_commit();
        cp_wait1();
        __syncthreads();

        const uint32_t* As = sm + p * kStageW;
        const uint32_t* Bs = As + kTileW;

        #pragma unroll
        for (int kk = 0; kk < 2; kk++) {          // two k16 steps
            const int w = kk * 8 + cA;            // k-word index
            uint32_t af[4][4];
            #pragma unroll
            for (int mt = 0; mt < 4; mt++) {
                const int r = wm * 64 + mt * 16 + rA;
                af[mt][0] = As[r * kWpad + w];
                af[mt][1] = As[(r + 8) * kWpad + w];
                af[mt][2] = As[r * kWpad + w + 4];
                af[mt][3] = As[(r + 8) * kWpad + w + 4];
            }
            uint32_t bf[4][2];
            #pragma unroll
            for (int nt = 0; nt < 4; nt++) {
                const int n = wn * 32 + nt * 8 + rA;
                bf[nt][0] = Bs[n * kWpad + w];
                bf[nt][1] = Bs[n * kWpad + w + 4];
            }
            #pragma unroll
            for (int mt = 0; mt < 4; mt++)
                #pragma unroll
                for (int nt = 0; nt < 4; nt++)
                    mma16(acc[mt][nt], af[mt], bf[nt]);
        }
        __syncthreads();
    }

    // ---- epilogue ----
    constexpr bool OUTB = (EPI == 0 || EPI == 1 || EPI == 3);
    #pragma unroll
    for (int mt = 0; mt < 4; mt++) {
        const int r0 = m0 + wm * 64 + mt * 16 + rA;
        float bm0 = 0.f, bm1 = 0.f;
        if (EPI == 1 || EPI == 4) { bm0 = bias[r0]; bm1 = bias[r0 + 8]; }
        #pragma unroll
        for (int nt = 0; nt < 4; nt++) {
            const int col = n0 + wn * 32 + nt * 8 + cA * 2;
            float d0 = acc[mt][nt][0], d1 = acc[mt][nt][1];
            float d2 = acc[mt][nt][2], d3 = acc[mt][nt][3];
            if (EPI == 0) {
                const float b0 = bias[col], b1 = bias[col + 1];
                d0 += b0; d1 += b1; d2 += b0; d3 += b1;
            } else if (EPI == 1 || EPI == 4) {
                d0 += bm0; d1 += bm0; d2 += bm1; d3 += bm1;
            } else if (EPI == 2) {
                d0 *= alpha; d1 *= alpha; d2 *= alpha; d3 *= alpha;
            }
            if (EPI == 4) {
                const float* rp = res + sC * bz;
                d0 += rp[(size_t)r0 * ldc + col];
                d1 += rp[(size_t)r0 * ldc + col + 1];
                d2 += rp[(size_t)(r0 + 8) * ldc + col];
                d3 += rp[(size_t)(r0 + 8) * ldc + col + 1];
            }
            if (OUTB) {
                __nv_bfloat16* Cb = (__nv_bfloat16*)Cv + sC * bz;
                *(__nv_bfloat162*)(Cb + (size_t)r0 * ldc + col) =
                    __floats2bfloat162_rn(d0, d1);
                *(__nv_bfloat162*)(Cb + (size_t)(r0 + 8) * ldc + col) =
                    __floats2bfloat162_rn(d2, d3);
            } else {
                float* Cb = (float*)Cv + sC * bz;
                *(float2*)(Cb + (size_t)r0 * ldc + col)       = make_float2(d0, d1);
                *(float2*)(Cb + (size_t)(r0 + 8) * ldc + col) = make_float2(d2, d3);
            }
        }
    }
}

// ---------------------------------------------------------------------------
// Row softmax over 4096 f32 logits -> bf16 attn; one block (256 thr) per row.
// ---------------------------------------------------------------------------
__global__ void softmax_kernel(const float* __restrict__ sim,
                               __nv_bfloat16* __restrict__ simh) {
    const float* p = sim + (size_t)blockIdx.x * kHW;
    __nv_bfloat16* ph = simh + (size_t)blockIdx.x * kHW;
    const int tid = threadIdx.x;
    float v[16];
    float mx = -1e30f;
    #pragma unroll
    for (int i = 0; i < 16; i++) {
        v[i] = p[tid + i * 256];
        mx = fmaxf(mx, v[i]);
    }
    __shared__ float sh[256];
    sh[tid] = mx; __syncthreads();
    for (int o = 128; o > 0; o >>= 1) {
        if (tid < o) sh[tid] = fmaxf(sh[tid], sh[tid + o]);
        __syncthreads();
    }
    mx = sh[0];
    __syncthreads();
    float s = 0.f;
    #pragma unroll
    for (int i = 0; i < 16; i++) { v[i] = __expf(v[i] - mx); s += v[i]; }
    sh[tid] = s; __syncthreads();
    for (int o = 128; o > 0; o >>= 1) {
        if (tid < o) sh[tid] += sh[tid + o];
        __syncthreads();
    }
    const float rinv = 1.f / sh[0];
    #pragma unroll
    for (int i = 0; i < 16; i++)
        ph[tid + i * 256] = __float2bfloat16_rn(v[i] * rinv);
}

// ---------------------------------------------------------------------------
extern "C" void kernel_launch(void* const* d_in, const int* in_sizes, int n_in,
                              void* d_out, int out_size) {
    const float* x     = (const float*)d_in[0];
    const float* gamma = (const float*)d_in[1];
    const float* beta  = (const float*)d_in[2];
    const float* wq    = (const float*)d_in[3];
    const float* bq    = (const float*)d_in[4];
    const float* wk    = (const float*)d_in[5];
    const float* bk    = (const float*)d_in[6];
    const float* wv    = (const float*)d_in[7];
    const float* bv    = (const float*)d_in[8];
    const float* wo    = (const float*)d_in[9];
    const float* bo    = (const float*)d_in[10];
    float* out = (float*)d_out;

    __nv_bfloat16 *hT, *qt, *kt, *v, *o2, *simh, *wh;
    float *sim, *aff;
    cudaGetSymbolAddress((void**)&hT,   g_hT);
    cudaGetSymbolAddress((void**)&qt,   g_qt);
    cudaGetSymbolAddress((void**)&kt,   g_kt);
    cudaGetSymbolAddress((void**)&v,    g_v);
    cudaGetSymbolAddress((void**)&o2,   g_o2);
    cudaGetSymbolAddress((void**)&sim,  g_sim);
    cudaGetSymbolAddress((void**)&simh, g_simh);
    cudaGetSymbolAddress((void**)&aff,  g_aff);
    cudaGetSymbolAddress((void**)&wh,   g_wh);

    const size_t sNC = (size_t)kHW * kC;    // per-batch [n][c] / [c][n]
    const size_t sNN = (size_t)kHW * kHW;   // per-batch sim
    const float  scale = 1.0f / sqrtf((float)kC);
    const int nW = kC * kC;

    // 0) weights -> bf16
    prep_weights<<<(nW + 255) / 256, 256>>>(wq, wk, wv, wo, wh);

    // 1) GroupNorm (stats + fused normalize-transpose-bf16)
    gn_stats<<<kB * kG, 256>>>(x, gamma, beta, aff);
    gn_norm_t<<<dim3(kHW / 32, kC / 32, kB), dim3(32, 8)>>>(x, aff, hT);

    // 2) Qt / Kt = hT @ W^T  (M=4096, N=512, K=512), bias over columns
    {
        dim3 grid(kC / 128, kHW / 128, kB);
        gemm_bf16<0><<<grid, 256>>>(hT, wh + 0 * nW, bq, nullptr, qt,
                                    kC, kC, kC, kC, sNC, 0, sNC, 1.f);
        gemm_bf16<0><<<grid, 256>>>(hT, wh + 1 * nW, bk, nullptr, kt,
                                    kC, kC, kC, kC, sNC, 0, sNC, 1.f);
    }
    // 3) V = Wv @ H  (M=512, N=4096, K=512), output [c][n], bias over rows
    {
        dim3 grid(kHW / 128, kC / 128, kB);
        gemm_bf16<1><<<grid, 256>>>(wh + 2 * nW, hT, bv, nullptr, v,
                                    kC, kC, kHW, kC, 0, sNC, sNC, 1.f);
    }
    // 4) sim = Qt @ Kt^T * scale  (M=N=4096, K=512), f32 out
    {
        dim3 grid(kHW / 128, kHW / 128, kB);
        gemm_bf16<2><<<grid, 256>>>(qt, kt, nullptr, nullptr, sim,
                                    kC, kC, kHW, kC, sNC, sNC, sNN, scale);
    }
    // 5) softmax rows -> bf16
    softmax_kernel<<<kB * kHW, 256>>>(sim, simh);

    // 6) o2 = attn @ V^T  (M=4096, N=512, K=4096), output [n][c] bf16
    {
        dim3 grid(kC / 128, kHW / 128, kB);
        gemm_bf16<3><<<grid, 256>>>(simh, v, nullptr, nullptr, o2,
                                    kHW, kHW, kC, kHW, sNN, sNC, sNC, 1.f);
    }
    // 7) out = x + Wo @ o2^T + bo  (M=512, N=4096, K=512), f32 out
    {
        dim3 grid(kHW / 128, kC / 128, kB);
        gemm_bf16<4><<<grid, 256>>>(wh + 3 * nW, o2, bo, x, out,
                                    kC, kC, kHW, kC, 0, sNC, sNC, 1.f);
    }
}

// round 7
// speedup vs baseline: 5.4945x; 1.0699x over previous
#include <cuda_runtime.h>
#include <cuda_bf16.h>
#include <cstdint>
#include <math.h>

// ---------------------------------------------------------------------------
// Problem constants
// ---------------------------------------------------------------------------
constexpr int kB  = 4;
constexpr int kC  = 512;
constexpr int kHW = 4096;
constexpr int kG  = 32;
constexpr int kCPG = kC / kG;   // 16
constexpr float kEPS = 1e-6f;

// Scratch (__device__ globals per allocation-free rule)
__device__ __nv_bfloat16 g_hT [(size_t)kB * kHW * kC];   // GN out [b][n][c]
__device__ __nv_bfloat16 g_qt [(size_t)kB * kHW * kC];   // Q^T [b][n][c]
__device__ __nv_bfloat16 g_kt [(size_t)kB * kHW * kC];   // K^T [b][n][c]
__device__ __nv_bfloat16 g_v  [(size_t)kB * kC * kHW];   // V   [b][c][n]
__device__ __nv_bfloat16 g_o2 [(size_t)kB * kHW * kC];   // attn@V [b][n][c]
__device__ float         g_sim [(size_t)kB * kHW * kHW]; // logits f32 (256 MB)
__device__ __nv_bfloat16 g_simh[(size_t)kB * kHW * kHW]; // attn bf16 (128 MB)
__device__ float         g_aff[(size_t)kB * kC * 2];     // (scale, offset)
__device__ __nv_bfloat16 g_wh [4 * kC * kC];             // bf16 wq,wk,wv,wo

// ---------------------------------------------------------------------------
// Helpers
// ---------------------------------------------------------------------------
__device__ __forceinline__ uint32_t smem_u32(const void* p) {
    uint32_t a;
    asm("{ .reg .u64 t; cvta.to.shared.u64 t, %1; cvt.u32.u64 %0, t; }"
        : "=r"(a) : "l"(p));
    return a;
}
__device__ __forceinline__ void cp16(uint32_t dst, const void* src) {
    asm volatile("cp.async.cg.shared.global [%0], [%1], 16;\n"
                 :: "r"(dst), "l"(src));
}
__device__ __forceinline__ void cp_commit() {
    asm volatile("cp.async.commit_group;\n" ::: "memory");
}
__device__ __forceinline__ void cp_wait1() {
    asm volatile("cp.async.wait_group 1;\n" ::: "memory");
}
// m16n8k16 bf16 mma, row.col, fp32 accum
__device__ __forceinline__ void mma16(float* d, const uint32_t* a, const uint32_t* b) {
    asm volatile(
        "mma.sync.aligned.m16n8k16.row.col.f32.bf16.bf16.f32 "
        "{%0,%1,%2,%3}, {%4,%5,%6,%7}, {%8,%9}, {%0,%1,%2,%3};"
        : "+f"(d[0]), "+f"(d[1]), "+f"(d[2]), "+f"(d[3])
        : "r"(a[0]), "r"(a[1]), "r"(a[2]), "r"(a[3]), "r"(b[0]), "r"(b[1]));
}
// ldmatrix 4x (m8n8 b16)
__device__ __forceinline__ void ldsm4(uint32_t* r, uint32_t addr) {
    asm volatile(
        "ldmatrix.sync.aligned.m8n8.x4.shared.b16 {%0,%1,%2,%3}, [%4];"
        : "=r"(r[0]), "=r"(r[1]), "=r"(r[2]), "=r"(r[3]) : "r"(addr));
}

// ---------------------------------------------------------------------------
// Weight prep: round 4 weight matrices to bf16
// ---------------------------------------------------------------------------
__global__ void prep_weights(const float* __restrict__ wq, const float* __restrict__ wk,
                             const float* __restrict__ wv, const float* __restrict__ wo,
                             __nv_bfloat16* __restrict__ wh) {
    const int i = blockIdx.x * blockDim.x + threadIdx.x;
    const int n = kC * kC;
    if (i < n) {
        wh[0 * n + i] = __float2bfloat16_rn(wq[i]);
        wh[1 * n + i] = __float2bfloat16_rn(wk[i]);
        wh[2 * n + i] = __float2bfloat16_rn(wv[i]);
        wh[3 * n + i] = __float2bfloat16_rn(wo[i]);
    }
}

// ---------------------------------------------------------------------------
// GroupNorm pass 1: per-(b,g) mean/var -> per-channel affine (a, b)
// ---------------------------------------------------------------------------
__global__ void gn_stats(const float* __restrict__ x,
                         const float* __restrict__ gamma,
                         const float* __restrict__ beta,
                         float* __restrict__ aff) {
    const int b = blockIdx.x / kG, g = blockIdx.x % kG;
    const float* xp = x + ((size_t)b * kC + (size_t)g * kCPG) * kHW;
    const int N = kCPG * kHW;

    float s = 0.f, ss = 0.f;
    for (int i = threadIdx.x; i < N; i += 256) {
        float v = xp[i];
        s += v; ss += v * v;
    }
    __shared__ float sh1[256], sh2[256];
    sh1[threadIdx.x] = s; sh2[threadIdx.x] = ss;
    __syncthreads();
    for (int o = 128; o > 0; o >>= 1) {
        if (threadIdx.x < o) {
            sh1[threadIdx.x] += sh1[threadIdx.x + o];
            sh2[threadIdx.x] += sh2[threadIdx.x + o];
        }
        __syncthreads();
    }
    if (threadIdx.x < kCPG) {
        const float mean = sh1[0] / (float)N;
        const float var  = sh2[0] / (float)N - mean * mean;
        const float rinv = rsqrtf(var + kEPS);
        const int ch = g * kCPG + threadIdx.x;
        const float a = rinv * gamma[ch];
        aff[((size_t)b * kC + ch) * 2 + 0] = a;
        aff[((size_t)b * kC + ch) * 2 + 1] = beta[ch] - mean * a;
    }
}

// ---------------------------------------------------------------------------
// GroupNorm pass 2: normalize + transpose + bf16: x[b][c][n] -> hT[b][n][c]
// ---------------------------------------------------------------------------
__global__ void gn_norm_t(const float* __restrict__ x,
                          const float* __restrict__ aff,
                          __nv_bfloat16* __restrict__ hT) {
    __shared__ float t[32][33];
    const int b = blockIdx.z;
    const int n0 = blockIdx.x * 32, c0 = blockIdx.y * 32;
    const int tx = threadIdx.x, ty = threadIdx.y;   // 32 x 8
    const float* xb = x  + (size_t)b * kC * kHW;
    __nv_bfloat16* hb = hT + (size_t)b * kHW * kC;

    #pragma unroll
    for (int r = 0; r < 4; r++) {
        const int c = c0 + ty + r * 8;
        const float a  = aff[((size_t)b * kC + c) * 2 + 0];
        const float bb = aff[((size_t)b * kC + c) * 2 + 1];
        t[ty + r * 8][tx] = xb[(size_t)c * kHW + n0 + tx] * a + bb;
    }
    __syncthreads();
    #pragma unroll
    for (int r = 0; r < 4; r++) {
        const int n = n0 + ty + r * 8;
        hb[(size_t)n * kC + c0 + tx] = __float2bfloat16_rn(t[tx][ty + r * 8]);
    }
}

// ---------------------------------------------------------------------------
// bf16 mma.sync GEMM: C[m][n] = sum_k A[m][k] * B[n][k]  (both K-major bf16)
// 128x128x32 tile, 256 threads, 8 warps (2x4), warp tile 64x32.
// Fragments loaded via ldmatrix.x4 (6 LDSM per k16 step instead of 24 LDS).
// __launch_bounds__(256, 2): 2 CTAs/SM.
// EPI: 0=+bias[n]->bf16, 1=+bias[m]->bf16, 2=*alpha->f32, 3=none->bf16,
//      4=+bias[m]+res[m][n]->f32
// ---------------------------------------------------------------------------
constexpr int kWpad   = 20;              // padded row stride (32-bit words)
constexpr int kTileW  = 128 * kWpad;     // 2560 words per tile (A or B)
constexpr int kStageW = 2 * kTileW;      // 5120 words per stage (A + B)

template <int EPI>
__global__ void __launch_bounds__(256, 2)
gemm_bf16(const __nv_bfloat16* __restrict__ A, const __nv_bfloat16* __restrict__ B,
          const float* __restrict__ bias, const float* __restrict__ res,
          void* __restrict__ Cv,
          int lda, int ldb, int ldc, int K,
          size_t sA, size_t sB, size_t sC, float alpha) {
    __shared__ __align__(16) uint32_t sm[2 * kStageW];   // 40,960 bytes
    const int tid = threadIdx.x;
    const int lane = tid & 31, wid = tid >> 5;
    const int wm = wid & 1, wn = wid >> 1;   // warp grid 2 x 4

    const int bz = blockIdx.z;
    const __nv_bfloat16* Ab = A + sA * bz;
    const __nv_bfloat16* Bb = B + sB * bz;
    const int m0 = blockIdx.y * 128;
    const int n0 = blockIdx.x * 128;

    const uint32_t smAddr = smem_u32(sm);
    const int KT = K / 32;

    // ldmatrix per-lane address offsets (in words, relative to tile base)
    const int lg   = lane >> 3;          // lane group 0..3
    const int lrow = lane & 7;
    // A x4: regs {a0,a1,a2,a3} = {(r,w),(r+8,w),(r,w+4),(r+8,w+4)}
    const int aRowOff = wm * 64 + (lg & 1) * 8 + lrow;
    const int aColOff = (lg >> 1) * 4;
    // B x4 (two n-tiles): regs {b(nt0)0,b(nt0)1,b(nt1)0,b(nt1)1}
    //   = {(n,w),(n,w+4),(n+8,w),(n+8,w+4)}
    const int bRowOff = wn * 32 + (lg >> 1) * 8 + lrow;
    const int bColOff = (lg & 1) * 4;

    // prefetch one 128x32(bf16) A tile + B tile into stage p
    auto prefetch = [&](int it, int p) {
        const int k0 = it * 32;
        const uint32_t aBase = smAddr + (uint32_t)(p * kStageW) * 4u;
        const uint32_t bBase = aBase + (uint32_t)kTileW * 4u;
        #pragma unroll
        for (int t = 0; t < 2; t++) {
            const int idx = t * 256 + tid;   // 0..511
            const int row = idx >> 2, seg = idx & 3;     // seg: 16B = 8 bf16
            const uint32_t so = (uint32_t)(row * kWpad + seg * 4) * 4u;
            cp16(aBase + so, Ab + (size_t)(m0 + row) * lda + k0 + seg * 8);
            cp16(bBase + so, Bb + (size_t)(n0 + row) * ldb + k0 + seg * 8);
        }
    };

    float acc[4][4][4];
    #pragma unroll
    for (int i = 0; i < 4; i++)
        #pragma unroll
        for (int j = 0; j < 4; j++)
            #pragma unroll
            for (int r = 0; r < 4; r++) acc[i][j][r] = 0.f;

    prefetch(0, 0);
    cp_commit();

    for (int it = 0; it < KT; ++it) {
        const int p = it & 1;
        if (it + 1 < KT) prefetch(it + 1, p ^ 1);
        cp_commit();
        cp_wait1();
        __syncthreads();

        const uint32_t aTile = smAddr + (uint32_t)(p * kStageW) * 4u;
        const uint32_t bTile = aTile + (uint32_t)kTileW * 4u;

        #pragma unroll
        for (int kk = 0; kk < 2; kk++) {          // two k16 steps
            uint32_t af[4][4];
            #pragma unroll
            for (int mt = 0; mt < 4; mt++)
                ldsm4(af[mt], aTile +
                      (uint32_t)((aRowOff + mt * 16) * kWpad + aColOff + kk * 8) * 4u);
            uint32_t bf[4][2];
            #pragma unroll
            for (int j = 0; j < 2; j++)
                ldsm4(&bf[2 * j][0], bTile +
                      (uint32_t)((bRowOff + j * 16) * kWpad + bColOff + kk * 8) * 4u);
            #pragma unroll
            for (int mt = 0; mt < 4; mt++)
                #pragma unroll
                for (int nt = 0; nt < 4; nt++)
                    mma16(acc[mt][nt], af[mt], bf[nt]);
        }
        __syncthreads();
    }

    // ---- epilogue ----
    constexpr bool OUTB = (EPI == 0 || EPI == 1 || EPI == 3);
    const int rA = lane >> 2, cA = lane & 3;
    #pragma unroll
    for (int mt = 0; mt < 4; mt++) {
        const int r0 = m0 + wm * 64 + mt * 16 + rA;
        float bm0 = 0.f, bm1 = 0.f;
        if (EPI == 1 || EPI == 4) { bm0 = bias[r0]; bm1 = bias[r0 + 8]; }
        #pragma unroll
        for (int nt = 0; nt < 4; nt++) {
            const int col = n0 + wn * 32 + nt * 8 + cA * 2;
            float d0 = acc[mt][nt][0], d1 = acc[mt][nt][1];
            float d2 = acc[mt][nt][2], d3 = acc[mt][nt][3];
            if (EPI == 0) {
                const float b0 = bias[col], b1 = bias[col + 1];
                d0 += b0; d1 += b1; d2 += b0; d3 += b1;
            } else if (EPI == 1 || EPI == 4) {
                d0 += bm0; d1 += bm0; d2 += bm1; d3 += bm1;
            } else if (EPI == 2) {
                d0 *= alpha; d1 *= alpha; d2 *= alpha; d3 *= alpha;
            }
            if (EPI == 4) {
                const float* rp = res + sC * bz;
                d0 += rp[(size_t)r0 * ldc + col];
                d1 += rp[(size_t)r0 * ldc + col + 1];
                d2 += rp[(size_t)(r0 + 8) * ldc + col];
                d3 += rp[(size_t)(r0 + 8) * ldc + col + 1];
            }
            if (OUTB) {
                __nv_bfloat16* Cb = (__nv_bfloat16*)Cv + sC * bz;
                *(__nv_bfloat162*)(Cb + (size_t)r0 * ldc + col) =
                    __floats2bfloat162_rn(d0, d1);
                *(__nv_bfloat162*)(Cb + (size_t)(r0 + 8) * ldc + col) =
                    __floats2bfloat162_rn(d2, d3);
            } else {
                float* Cb = (float*)Cv + sC * bz;
                *(float2*)(Cb + (size_t)r0 * ldc + col)       = make_float2(d0, d1);
                *(float2*)(Cb + (size_t)(r0 + 8) * ldc + col) = make_float2(d2, d3);
            }
        }
    }
}

// ---------------------------------------------------------------------------
// Row softmax over 4096 f32 logits -> bf16 attn; one block (256 thr) per row.
// ---------------------------------------------------------------------------
__global__ void softmax_kernel(const float* __restrict__ sim,
                               __nv_bfloat16* __restrict__ simh) {
    const float* p = sim + (size_t)blockIdx.x * kHW;
    __nv_bfloat16* ph = simh + (size_t)blockIdx.x * kHW;
    const int tid = threadIdx.x;
    float v[16];
    float mx = -1e30f;
    #pragma unroll
    for (int i = 0; i < 16; i++) {
        v[i] = p[tid + i * 256];
        mx = fmaxf(mx, v[i]);
    }
    __shared__ float sh[256];
    sh[tid] = mx; __syncthreads();
    for (int o = 128; o > 0; o >>= 1) {
        if (tid < o) sh[tid] = fmaxf(sh[tid], sh[tid + o]);
        __syncthreads();
    }
    mx = sh[0];
    __syncthreads();
    float s = 0.f;
    #pragma unroll
    for (int i = 0; i < 16; i++) { v[i] = __expf(v[i] - mx); s += v[i]; }
    sh[tid] = s; __syncthreads();
    for (int o = 128; o > 0; o >>= 1) {
        if (tid < o) sh[tid] += sh[tid + o];
        __syncthreads();
    }
    const float rinv = 1.f / sh[0];
    #pragma unroll
    for (int i = 0; i < 16; i++)
        ph[tid + i * 256] = __float2bfloat16_rn(v[i] * rinv);
}

// ---------------------------------------------------------------------------
extern "C" void kernel_launch(void* const* d_in, const int* in_sizes, int n_in,
                              void* d_out, int out_size) {
    const float* x     = (const float*)d_in[0];
    const float* gamma = (const float*)d_in[1];
    const float* beta  = (const float*)d_in[2];
    const float* wq    = (const float*)d_in[3];
    const float* bq    = (const float*)d_in[4];
    const float* wk    = (const float*)d_in[5];
    const float* bk    = (const float*)d_in[6];
    const float* wv    = (const float*)d_in[7];
    const float* bv    = (const float*)d_in[8];
    const float* wo    = (const float*)d_in[9];
    const float* bo    = (const float*)d_in[10];
    float* out = (float*)d_out;

    __nv_bfloat16 *hT, *qt, *kt, *v, *o2, *simh, *wh;
    float *sim, *aff;
    cudaGetSymbolAddress((void**)&hT,   g_hT);
    cudaGetSymbolAddress((void**)&qt,   g_qt);
    cudaGetSymbolAddress((void**)&kt,   g_kt);
    cudaGetSymbolAddress((void**)&v,    g_v);
    cudaGetSymbolAddress((void**)&o2,   g_o2);
    cudaGetSymbolAddress((void**)&sim,  g_sim);
    cudaGetSymbolAddress((void**)&simh, g_simh);
    cudaGetSymbolAddress((void**)&aff,  g_aff);
    cudaGetSymbolAddress((void**)&wh,   g_wh);

    const size_t sNC = (size_t)kHW * kC;    // per-batch [n][c] / [c][n]
    const size_t sNN = (size_t)kHW * kHW;   // per-batch sim
    const float  scale = 1.0f / sqrtf((float)kC);
    const int nW = kC * kC;

    // 0) weights -> bf16
    prep_weights<<<(nW + 255) / 256, 256>>>(wq, wk, wv, wo, wh);

    // 1) GroupNorm (stats + fused normalize-transpose-bf16)
    gn_stats<<<kB * kG, 256>>>(x, gamma, beta, aff);
    gn_norm_t<<<dim3(kHW / 32, kC / 32, kB), dim3(32, 8)>>>(x, aff, hT);

    // 2) Qt / Kt = hT @ W^T  (M=4096, N=512, K=512), bias over columns
    {
        dim3 grid(kC / 128, kHW / 128, kB);
        gemm_bf16<0><<<grid, 256>>>(hT, wh + 0 * nW, bq, nullptr, qt,
                                    kC, kC, kC, kC, sNC, 0, sNC, 1.f);
        gemm_bf16<0><<<grid, 256>>>(hT, wh + 1 * nW, bk, nullptr, kt,
                                    kC, kC, kC, kC, sNC, 0, sNC, 1.f);
    }
    // 3) V = Wv @ H  (M=512, N=4096, K=512), output [c][n], bias over rows
    {
        dim3 grid(kHW / 128, kC / 128, kB);
        gemm_bf16<1><<<grid, 256>>>(wh + 2 * nW, hT, bv, nullptr, v,
                                    kC, kC, kHW, kC, 0, sNC, sNC, 1.f);
    }
    // 4) sim = Qt @ Kt^T * scale  (M=N=4096, K=512), f32 out
    {
        dim3 grid(kHW / 128, kHW / 128, kB);
        gemm_bf16<2><<<grid, 256>>>(qt, kt, nullptr, nullptr, sim,
                                    kC, kC, kHW, kC, sNC, sNC, sNN, scale);
    }
    // 5) softmax rows -> bf16
    softmax_kernel<<<kB * kHW, 256>>>(sim, simh);

    // 6) o2 = attn @ V^T  (M=4096, N=512, K=4096), output [n][c] bf16
    {
        dim3 grid(kC / 128, kHW / 128, kB);
        gemm_bf16<3><<<grid, 256>>>(simh, v, nullptr, nullptr, o2,
                                    kHW, kHW, kC, kHW, sNN, sNC, sNC, 1.f);
    }
    // 7) out = x + Wo @ o2^T + bo  (M=512, N=4096, K=512), f32 out
    {
        dim3 grid(kHW / 128, kC / 128, kB);
        gemm_bf16<4><<<grid, 256>>>(wh + 3 * nW, o2, bo, x, out,
                                    kC, kC, kHW, kC, 0, sNC, sNC, 1.f);
    }
}

// round 8
// speedup vs baseline: 6.0925x; 1.1088x over previous
#include <cuda_runtime.h>
#include <cuda_bf16.h>
#include <cstdint>
#include <math.h>

// ---------------------------------------------------------------------------
// Problem constants
// ---------------------------------------------------------------------------
constexpr int kB  = 4;
constexpr int kC  = 512;
constexpr int kHW = 4096;
constexpr int kG  = 32;
constexpr int kCPG = kC / kG;   // 16
constexpr float kEPS = 1e-6f;

// Scratch (__device__ globals per allocation-free rule)
__device__ __nv_bfloat16 g_hT [(size_t)kB * kHW * kC];   // GN out [b][n][c]
__device__ __nv_bfloat16 g_qt [(size_t)kB * kHW * kC];   // Q^T [b][n][c]
__device__ __nv_bfloat16 g_kt [(size_t)kB * kHW * kC];   // K^T [b][n][c]
__device__ __nv_bfloat16 g_v  [(size_t)kB * kC * kHW];   // V   [b][c][n]
__device__ __nv_bfloat16 g_o2 [(size_t)kB * kHW * kC];   // attn@V [b][n][c]
__device__ float         g_sim [(size_t)kB * kHW * kHW]; // logits f32 (256 MB)
__device__ __nv_bfloat16 g_simh[(size_t)kB * kHW * kHW]; // attn bf16 (128 MB)
__device__ float         g_aff[(size_t)kB * kC * 2];     // (scale, offset)
__device__ __nv_bfloat16 g_wh [4 * kC * kC];             // bf16 wq,wk,wv,wo

// ---------------------------------------------------------------------------
// Helpers
// ---------------------------------------------------------------------------
__device__ __forceinline__ uint32_t smem_u32(const void* p) {
    uint32_t a;
    asm("{ .reg .u64 t; cvta.to.shared.u64 t, %1; cvt.u32.u64 %0, t; }"
        : "=r"(a) : "l"(p));
    return a;
}
__device__ __forceinline__ void cp16(uint32_t dst, const void* src) {
    asm volatile("cp.async.cg.shared.global [%0], [%1], 16;\n"
                 :: "r"(dst), "l"(src));
}
__device__ __forceinline__ void cp_commit() {
    asm volatile("cp.async.commit_group;\n" ::: "memory");
}
template <int N>
__device__ __forceinline__ void cp_wait() {
    asm volatile("cp.async.wait_group %0;\n" :: "n"(N) : "memory");
}
// m16n8k16 bf16 mma, row.col, fp32 accum
__device__ __forceinline__ void mma16(float* d, const uint32_t* a, const uint32_t* b) {
    asm volatile(
        "mma.sync.aligned.m16n8k16.row.col.f32.bf16.bf16.f32 "
        "{%0,%1,%2,%3}, {%4,%5,%6,%7}, {%8,%9}, {%0,%1,%2,%3};"
        : "+f"(d[0]), "+f"(d[1]), "+f"(d[2]), "+f"(d[3])
        : "r"(a[0]), "r"(a[1]), "r"(a[2]), "r"(a[3]), "r"(b[0]), "r"(b[1]));
}
// ldmatrix 4x (m8n8 b16)
__device__ __forceinline__ void ldsm4(uint32_t* r, uint32_t addr) {
    asm volatile(
        "ldmatrix.sync.aligned.m8n8.x4.shared.b16 {%0,%1,%2,%3}, [%4];"
        : "=r"(r[0]), "=r"(r[1]), "=r"(r[2]), "=r"(r[3]) : "r"(addr));
}

// ---------------------------------------------------------------------------
// Weight prep: round 4 weight matrices to bf16
// ---------------------------------------------------------------------------
__global__ void prep_weights(const float* __restrict__ wq, const float* __restrict__ wk,
                             const float* __restrict__ wv, const float* __restrict__ wo,
                             __nv_bfloat16* __restrict__ wh) {
    const int i = blockIdx.x * blockDim.x + threadIdx.x;
    const int n = kC * kC;
    if (i < n) {
        wh[0 * n + i] = __float2bfloat16_rn(wq[i]);
        wh[1 * n + i] = __float2bfloat16_rn(wk[i]);
        wh[2 * n + i] = __float2bfloat16_rn(wv[i]);
        wh[3 * n + i] = __float2bfloat16_rn(wo[i]);
    }
}

// ---------------------------------------------------------------------------
// GroupNorm pass 1: per-(b,g) mean/var -> per-channel affine (a, b)
// ---------------------------------------------------------------------------
__global__ void gn_stats(const float* __restrict__ x,
                         const float* __restrict__ gamma,
                         const float* __restrict__ beta,
                         float* __restrict__ aff) {
    const int b = blockIdx.x / kG, g = blockIdx.x % kG;
    const float* xp = x + ((size_t)b * kC + (size_t)g * kCPG) * kHW;
    const int N = kCPG * kHW;

    float s = 0.f, ss = 0.f;
    for (int i = threadIdx.x; i < N; i += 256) {
        float v = xp[i];
        s += v; ss += v * v;
    }
    __shared__ float sh1[256], sh2[256];
    sh1[threadIdx.x] = s; sh2[threadIdx.x] = ss;
    __syncthreads();
    for (int o = 128; o > 0; o >>= 1) {
        if (threadIdx.x < o) {
            sh1[threadIdx.x] += sh1[threadIdx.x + o];
            sh2[threadIdx.x] += sh2[threadIdx.x + o];
        }
        __syncthreads();
    }
    if (threadIdx.x < kCPG) {
        const float mean = sh1[0] / (float)N;
        const float var  = sh2[0] / (float)N - mean * mean;
        const float rinv = rsqrtf(var + kEPS);
        const int ch = g * kCPG + threadIdx.x;
        const float a = rinv * gamma[ch];
        aff[((size_t)b * kC + ch) * 2 + 0] = a;
        aff[((size_t)b * kC + ch) * 2 + 1] = beta[ch] - mean * a;
    }
}

// ---------------------------------------------------------------------------
// GroupNorm pass 2: normalize + transpose + bf16: x[b][c][n] -> hT[b][n][c]
// ---------------------------------------------------------------------------
__global__ void gn_norm_t(const float* __restrict__ x,
                          const float* __restrict__ aff,
                          __nv_bfloat16* __restrict__ hT) {
    __shared__ float t[32][33];
    const int b = blockIdx.z;
    const int n0 = blockIdx.x * 32, c0 = blockIdx.y * 32;
    const int tx = threadIdx.x, ty = threadIdx.y;   // 32 x 8
    const float* xb = x  + (size_t)b * kC * kHW;
    __nv_bfloat16* hb = hT + (size_t)b * kHW * kC;

    #pragma unroll
    for (int r = 0; r < 4; r++) {
        const int c = c0 + ty + r * 8;
        const float a  = aff[((size_t)b * kC + c) * 2 + 0];
        const float bb = aff[((size_t)b * kC + c) * 2 + 1];
        t[ty + r * 8][tx] = xb[(size_t)c * kHW + n0 + tx] * a + bb;
    }
    __syncthreads();
    #pragma unroll
    for (int r = 0; r < 4; r++) {
        const int n = n0 + ty + r * 8;
        hb[(size_t)n * kC + c0 + tx] = __float2bfloat16_rn(t[tx][ty + r * 8]);
    }
}

// ---------------------------------------------------------------------------
// bf16 mma.sync GEMM: C[m][n] = sum_k A[m][k] * B[n][k]  (both K-major bf16)
// 128x128x16 tile, 5-stage cp.async pipeline, swizzled smem (no padding).
// 256 threads, 8 warps (2x4), warp tile 64x32. 2 CTAs/SM.
// Tile: 128 rows x 16 bf16 = 32 B/row; 16B chunk swizzle c ^= (row>>2)&1.
// EPI: 0=+bias[n]->bf16, 1=+bias[m]->bf16, 2=*alpha->f32, 3=none->bf16,
//      4=+bias[m]+res[m][n]->f32
// ---------------------------------------------------------------------------
constexpr int kRowW   = 8;               // words per tile row (16 bf16)
constexpr int kTileW  = 128 * kRowW;     // 1024 words = 4 KB per tile
constexpr int kStageW = 2 * kTileW;      // A + B = 8 KB per stage
constexpr int kNS     = 5;               // pipeline stages (40 KB total)

__device__ __forceinline__ uint32_t swoff(int row, int c) {
    // word offset of 16B chunk c in swizzled tile
    return (uint32_t)(row * kRowW + ((c ^ ((row >> 2) & 1)) << 2));
}

template <int EPI>
__global__ void __launch_bounds__(256, 2)
gemm_bf16(const __nv_bfloat16* __restrict__ A, const __nv_bfloat16* __restrict__ B,
          const float* __restrict__ bias, const float* __restrict__ res,
          void* __restrict__ Cv,
          int lda, int ldb, int ldc, int K,
          size_t sA, size_t sB, size_t sC, float alpha) {
    __shared__ __align__(16) uint32_t sm[kNS * kStageW];   // 40,960 bytes
    const int tid = threadIdx.x;
    const int lane = tid & 31, wid = tid >> 5;
    const int wm = wid & 1, wn = wid >> 1;   // warp grid 2 x 4

    const int bz = blockIdx.z;
    const __nv_bfloat16* Ab = A + sA * bz;
    const __nv_bfloat16* Bb = B + sB * bz;
    const int m0 = blockIdx.y * 128;
    const int n0 = blockIdx.x * 128;

    const uint32_t smAddr = smem_u32(sm);
    const int KT = K / 16;

    // ldmatrix lane decomposition
    const int lg   = lane >> 3;          // lane group 0..3
    const int lrow = lane & 7;
    // A x4: {(m,k0),(m+8,k0),(m,k1),(m+8,k1)}; row=m, chunk=(lg>>1)
    const int aRow = wm * 64 + (lg & 1) * 8 + lrow;
    const int aChk = lg >> 1;
    // B x4 (two n-tiles): {(n,k0),(n,k1),(n+8,k0),(n+8,k1)}; row=n, chunk=(lg&1)
    const int bRow = wn * 32 + (lg >> 1) * 8 + lrow;
    const int bChk = lg & 1;

    // prefetch k-block it into stage s: thread loads one 16B A chunk + one B
    auto prefetch = [&](int it, int s) {
        const int k0 = it * 16;
        const int row = tid >> 1, c = tid & 1;
        const uint32_t aBase = smAddr + (uint32_t)(s * kStageW) * 4u;
        cp16(aBase + swoff(row, c) * 4u,
             Ab + (size_t)(m0 + row) * lda + k0 + c * 8);
        cp16(aBase + (uint32_t)kTileW * 4u + swoff(row, c) * 4u,
             Bb + (size_t)(n0 + row) * ldb + k0 + c * 8);
    };

    float acc[4][4][4];
    #pragma unroll
    for (int i = 0; i < 4; i++)
        #pragma unroll
        for (int j = 0; j < 4; j++)
            #pragma unroll
            for (int r = 0; r < 4; r++) acc[i][j][r] = 0.f;

    #pragma unroll
    for (int s = 0; s < kNS - 1; s++) {
        prefetch(s, s);
        cp_commit();
    }

    for (int it = 0; it < KT; ++it) {
        cp_wait<kNS - 2>();          // stage it%kNS data resident
        __syncthreads();             // all warps done with stage (it+kNS-1)%kNS

        if (it + kNS - 1 < KT) prefetch(it + kNS - 1, (it + kNS - 1) % kNS);
        cp_commit();

        const uint32_t aTile = smAddr + (uint32_t)((it % kNS) * kStageW) * 4u;
        const uint32_t bTile = aTile + (uint32_t)kTileW * 4u;

        uint32_t af[4][4];
        #pragma unroll
        for (int mt = 0; mt < 4; mt++)
            ldsm4(af[mt], aTile + swoff(aRow + mt * 16, aChk) * 4u);
        uint32_t bf[4][2];
        #pragma unroll
        for (int j = 0; j < 2; j++)
            ldsm4(&bf[2 * j][0], bTile + swoff(bRow + j * 16, bChk) * 4u);

        #pragma unroll
        for (int mt = 0; mt < 4; mt++)
            #pragma unroll
            for (int nt = 0; nt < 4; nt++)
                mma16(acc[mt][nt], af[mt], bf[nt]);
    }

    // ---- epilogue ----
    constexpr bool OUTB = (EPI == 0 || EPI == 1 || EPI == 3);
    const int rA = lane >> 2, cA = lane & 3;
    #pragma unroll
    for (int mt = 0; mt < 4; mt++) {
        const int r0 = m0 + wm * 64 + mt * 16 + rA;
        float bm0 = 0.f, bm1 = 0.f;
        if (EPI == 1 || EPI == 4) { bm0 = bias[r0]; bm1 = bias[r0 + 8]; }
        #pragma unroll
        for (int nt = 0; nt < 4; nt++) {
            const int col = n0 + wn * 32 + nt * 8 + cA * 2;
            float d0 = acc[mt][nt][0], d1 = acc[mt][nt][1];
            float d2 = acc[mt][nt][2], d3 = acc[mt][nt][3];
            if (EPI == 0) {
                const float b0 = bias[col], b1 = bias[col + 1];
                d0 += b0; d1 += b1; d2 += b0; d3 += b1;
            } else if (EPI == 1 || EPI == 4) {
                d0 += bm0; d1 += bm0; d2 += bm1; d3 += bm1;
            } else if (EPI == 2) {
                d0 *= alpha; d1 *= alpha; d2 *= alpha; d3 *= alpha;
            }
            if (EPI == 4) {
                const float* rp = res + sC * bz;
                d0 += rp[(size_t)r0 * ldc + col];
                d1 += rp[(size_t)r0 * ldc + col + 1];
                d2 += rp[(size_t)(r0 + 8) * ldc + col];
                d3 += rp[(size_t)(r0 + 8) * ldc + col + 1];
            }
            if (OUTB) {
                __nv_bfloat16* Cb = (__nv_bfloat16*)Cv + sC * bz;
                *(__nv_bfloat162*)(Cb + (size_t)r0 * ldc + col) =
                    __floats2bfloat162_rn(d0, d1);
                *(__nv_bfloat162*)(Cb + (size_t)(r0 + 8) * ldc + col) =
                    __floats2bfloat162_rn(d2, d3);
            } else {
                float* Cb = (float*)Cv + sC * bz;
                *(float2*)(Cb + (size_t)r0 * ldc + col)       = make_float2(d0, d1);
                *(float2*)(Cb + (size_t)(r0 + 8) * ldc + col) = make_float2(d2, d3);
            }
        }
    }
}

// ---------------------------------------------------------------------------
// Row softmax over 4096 f32 logits -> bf16 attn; one block (256 thr) per row.
// ---------------------------------------------------------------------------
__global__ void softmax_kernel(const float* __restrict__ sim,
                               __nv_bfloat16* __restrict__ simh) {
    const float* p = sim + (size_t)blockIdx.x * kHW;
    __nv_bfloat16* ph = simh + (size_t)blockIdx.x * kHW;
    const int tid = threadIdx.x;
    float v[16];
    float mx = -1e30f;
    #pragma unroll
    for (int i = 0; i < 16; i++) {
        v[i] = p[tid + i * 256];
        mx = fmaxf(mx, v[i]);
    }
    __shared__ float sh[256];
    sh[tid] = mx; __syncthreads();
    for (int o = 128; o > 0; o >>= 1) {
        if (tid < o) sh[tid] = fmaxf(sh[tid], sh[tid + o]);
        __syncthreads();
    }
    mx = sh[0];
    __syncthreads();
    float s = 0.f;
    #pragma unroll
    for (int i = 0; i < 16; i++) { v[i] = __expf(v[i] - mx); s += v[i]; }
    sh[tid] = s; __syncthreads();
    for (int o = 128; o > 0; o >>= 1) {
        if (tid < o) sh[tid] += sh[tid + o];
        __syncthreads();
    }
    const float rinv = 1.f / sh[0];
    #pragma unroll
    for (int i = 0; i < 16; i++)
        ph[tid + i * 256] = __float2bfloat16_rn(v[i] * rinv);
}

// ---------------------------------------------------------------------------
extern "C" void kernel_launch(void* const* d_in, const int* in_sizes, int n_in,
                              void* d_out, int out_size) {
    const float* x     = (const float*)d_in[0];
    const float* gamma = (const float*)d_in[1];
    const float* beta  = (const float*)d_in[2];
    const float* wq    = (const float*)d_in[3];
    const float* bq    = (const float*)d_in[4];
    const float* wk    = (const float*)d_in[5];
    const float* bk    = (const float*)d_in[6];
    const float* wv    = (const float*)d_in[7];
    const float* bv    = (const float*)d_in[8];
    const float* wo    = (const float*)d_in[9];
    const float* bo    = (const float*)d_in[10];
    float* out = (float*)d_out;

    __nv_bfloat16 *hT, *qt, *kt, *v, *o2, *simh, *wh;
    float *sim, *aff;
    cudaGetSymbolAddress((void**)&hT,   g_hT);
    cudaGetSymbolAddress((void**)&qt,   g_qt);
    cudaGetSymbolAddress((void**)&kt,   g_kt);
    cudaGetSymbolAddress((void**)&v,    g_v);
    cudaGetSymbolAddress((void**)&o2,   g_o2);
    cudaGetSymbolAddress((void**)&sim,  g_sim);
    cudaGetSymbolAddress((void**)&simh, g_simh);
    cudaGetSymbolAddress((void**)&aff,  g_aff);
    cudaGetSymbolAddress((void**)&wh,   g_wh);

    const size_t sNC = (size_t)kHW * kC;    // per-batch [n][c] / [c][n]
    const size_t sNN = (size_t)kHW * kHW;   // per-batch sim
    const float  scale = 1.0f / sqrtf((float)kC);
    const int nW = kC * kC;

    // 0) weights -> bf16
    prep_weights<<<(nW + 255) / 256, 256>>>(wq, wk, wv, wo, wh);

    // 1) GroupNorm (stats + fused normalize-transpose-bf16)
    gn_stats<<<kB * kG, 256>>>(x, gamma, beta, aff);
    gn_norm_t<<<dim3(kHW / 32, kC / 32, kB), dim3(32, 8)>>>(x, aff, hT);

    // 2) Qt / Kt = hT @ W^T  (M=4096, N=512, K=512), bias over columns
    {
        dim3 grid(kC / 128, kHW / 128, kB);
        gemm_bf16<0><<<grid, 256>>>(hT, wh + 0 * nW, bq, nullptr, qt,
                                    kC, kC, kC, kC, sNC, 0, sNC, 1.f);
        gemm_bf16<0><<<grid, 256>>>(hT, wh + 1 * nW, bk, nullptr, kt,
                                    kC, kC, kC, kC, sNC, 0, sNC, 1.f);
    }
    // 3) V = Wv @ H  (M=512, N=4096, K=512), output [c][n], bias over rows
    {
        dim3 grid(kHW / 128, kC / 128, kB);
        gemm_bf16<1><<<grid, 256>>>(wh + 2 * nW, hT, bv, nullptr, v,
                                    kC, kC, kHW, kC, 0, sNC, sNC, 1.f);
    }
    // 4) sim = Qt @ Kt^T * scale  (M=N=4096, K=512), f32 out
    {
        dim3 grid(kHW / 128, kHW / 128, kB);
        gemm_bf16<2><<<grid, 256>>>(qt, kt, nullptr, nullptr, sim,
                                    kC, kC, kHW, kC, sNC, sNC, sNN, scale);
    }
    // 5) softmax rows -> bf16
    softmax_kernel<<<kB * kHW, 256>>>(sim, simh);

    // 6) o2 = attn @ V^T  (M=4096, N=512, K=4096), output [n][c] bf16
    {
        dim3 grid(kC / 128, kHW / 128, kB);
        gemm_bf16<3><<<grid, 256>>>(simh, v, nullptr, nullptr, o2,
                                    kHW, kHW, kC, kHW, sNN, sNC, sNC, 1.f);
    }
    // 7) out = x + Wo @ o2^T + bo  (M=512, N=4096, K=512), f32 out
    {
        dim3 grid(kHW / 128, kC / 128, kB);
        gemm_bf16<4><<<grid, 256>>>(wh + 3 * nW, o2, bo, x, out,
                                    kC, kC, kHW, kC, 0, sNC, sNC, 1.f);
    }
}

// round 9
// speedup vs baseline: 6.6433x; 1.0904x over previous
#include <cuda_runtime.h>
#include <cuda_bf16.h>
#include <cstdint>
#include <math.h>

// ---------------------------------------------------------------------------
// Problem constants
// ---------------------------------------------------------------------------
constexpr int kB  = 4;
constexpr int kC  = 512;
constexpr int kHW = 4096;
constexpr int kG  = 32;
constexpr int kCPG = kC / kG;   // 16
constexpr float kEPS = 1e-6f;

// Scratch (__device__ globals per allocation-free rule)
__device__ __nv_bfloat16 g_hT [(size_t)kB * kHW * kC];   // GN out [b][n][c]
__device__ __nv_bfloat16 g_qt [(size_t)kB * kHW * kC];   // Q^T [b][n][c]
__device__ __nv_bfloat16 g_kt [(size_t)kB * kHW * kC];   // K^T [b][n][c]
__device__ __nv_bfloat16 g_v  [(size_t)kB * kC * kHW];   // V   [b][c][n]
__device__ __nv_bfloat16 g_o2 [(size_t)kB * kHW * kC];   // attn@V [b][n][c]
__device__ float         g_sim [(size_t)kB * kHW * kHW]; // logits f32 (256 MB)
__device__ __nv_bfloat16 g_simh[(size_t)kB * kHW * kHW]; // attn bf16 (128 MB)
__device__ float         g_aff[(size_t)kB * kC * 2];     // (scale, offset)
__device__ __nv_bfloat16 g_wh [4 * kC * kC];             // bf16 wq,wk,wv,wo

// ---------------------------------------------------------------------------
// Helpers
// ---------------------------------------------------------------------------
__device__ __forceinline__ uint32_t smem_u32(const void* p) {
    uint32_t a;
    asm("{ .reg .u64 t; cvta.to.shared.u64 t, %1; cvt.u32.u64 %0, t; }"
        : "=r"(a) : "l"(p));
    return a;
}
__device__ __forceinline__ void cp16(uint32_t dst, const void* src) {
    asm volatile("cp.async.cg.shared.global [%0], [%1], 16;\n"
                 :: "r"(dst), "l"(src));
}
__device__ __forceinline__ void cp_commit() {
    asm volatile("cp.async.commit_group;\n" ::: "memory");
}
template <int N>
__device__ __forceinline__ void cp_wait() {
    asm volatile("cp.async.wait_group %0;\n" :: "n"(N) : "memory");
}
// m16n8k16 bf16 mma, row.col, fp32 accum
__device__ __forceinline__ void mma16(float* d, const uint32_t* a, const uint32_t* b) {
    asm volatile(
        "mma.sync.aligned.m16n8k16.row.col.f32.bf16.bf16.f32 "
        "{%0,%1,%2,%3}, {%4,%5,%6,%7}, {%8,%9}, {%0,%1,%2,%3};"
        : "+f"(d[0]), "+f"(d[1]), "+f"(d[2]), "+f"(d[3])
        : "r"(a[0]), "r"(a[1]), "r"(a[2]), "r"(a[3]), "r"(b[0]), "r"(b[1]));
}
// ldmatrix 4x (m8n8 b16)
__device__ __forceinline__ void ldsm4(uint32_t* r, uint32_t addr) {
    asm volatile(
        "ldmatrix.sync.aligned.m8n8.x4.shared.b16 {%0,%1,%2,%3}, [%4];"
        : "=r"(r[0]), "=r"(r[1]), "=r"(r[2]), "=r"(r[3]) : "r"(addr));
}

// ---------------------------------------------------------------------------
// Weight prep: round 4 weight matrices to bf16
// ---------------------------------------------------------------------------
__global__ void prep_weights(const float* __restrict__ wq, const float* __restrict__ wk,
                             const float* __restrict__ wv, const float* __restrict__ wo,
                             __nv_bfloat16* __restrict__ wh) {
    const int i = blockIdx.x * blockDim.x + threadIdx.x;
    const int n = kC * kC;
    if (i < n) {
        wh[0 * n + i] = __float2bfloat16_rn(wq[i]);
        wh[1 * n + i] = __float2bfloat16_rn(wk[i]);
        wh[2 * n + i] = __float2bfloat16_rn(wv[i]);
        wh[3 * n + i] = __float2bfloat16_rn(wo[i]);
    }
}

// ---------------------------------------------------------------------------
// GroupNorm pass 1: per-(b,g) mean/var -> per-channel affine (a, b)
// ---------------------------------------------------------------------------
__global__ void gn_stats(const float* __restrict__ x,
                         const float* __restrict__ gamma,
                         const float* __restrict__ beta,
                         float* __restrict__ aff) {
    const int b = blockIdx.x / kG, g = blockIdx.x % kG;
    const float* xp = x + ((size_t)b * kC + (size_t)g * kCPG) * kHW;
    const int N = kCPG * kHW;

    float s = 0.f, ss = 0.f;
    for (int i = threadIdx.x; i < N; i += 256) {
        float v = xp[i];
        s += v; ss += v * v;
    }
    __shared__ float sh1[256], sh2[256];
    sh1[threadIdx.x] = s; sh2[threadIdx.x] = ss;
    __syncthreads();
    for (int o = 128; o > 0; o >>= 1) {
        if (threadIdx.x < o) {
            sh1[threadIdx.x] += sh1[threadIdx.x + o];
            sh2[threadIdx.x] += sh2[threadIdx.x + o];
        }
        __syncthreads();
    }
    if (threadIdx.x < kCPG) {
        const float mean = sh1[0] / (float)N;
        const float var  = sh2[0] / (float)N - mean * mean;
        const float rinv = rsqrtf(var + kEPS);
        const int ch = g * kCPG + threadIdx.x;
        const float a = rinv * gamma[ch];
        aff[((size_t)b * kC + ch) * 2 + 0] = a;
        aff[((size_t)b * kC + ch) * 2 + 1] = beta[ch] - mean * a;
    }
}

// ---------------------------------------------------------------------------
// GroupNorm pass 2: normalize + transpose + bf16: x[b][c][n] -> hT[b][n][c]
// ---------------------------------------------------------------------------
__global__ void gn_norm_t(const float* __restrict__ x,
                          const float* __restrict__ aff,
                          __nv_bfloat16* __restrict__ hT) {
    __shared__ float t[32][33];
    const int b = blockIdx.z;
    const int n0 = blockIdx.x * 32, c0 = blockIdx.y * 32;
    const int tx = threadIdx.x, ty = threadIdx.y;   // 32 x 8
    const float* xb = x  + (size_t)b * kC * kHW;
    __nv_bfloat16* hb = hT + (size_t)b * kHW * kC;

    #pragma unroll
    for (int r = 0; r < 4; r++) {
        const int c = c0 + ty + r * 8;
        const float a  = aff[((size_t)b * kC + c) * 2 + 0];
        const float bb = aff[((size_t)b * kC + c) * 2 + 1];
        t[ty + r * 8][tx] = xb[(size_t)c * kHW + n0 + tx] * a + bb;
    }
    __syncthreads();
    #pragma unroll
    for (int r = 0; r < 4; r++) {
        const int n = n0 + ty + r * 8;
        hb[(size_t)n * kC + c0 + tx] = __float2bfloat16_rn(t[tx][ty + r * 8]);
    }
}

// ---------------------------------------------------------------------------
// bf16 mma.sync GEMM: C[m][n] = sum_k A[m][k] * B[n][k]  (both K-major bf16)
// 128x128x32 tile, 3-stage cp.async pipeline, swizzled smem, 48KB static.
// 256 threads, 8 warps (2x4), warp tile 64x32. 2 CTAs/SM.
// Tile row = 32 bf16 = 64 B = 4 chunks of 16B; swizzle c ^= (row>>1)&3.
// One __syncthreads per BK=32 (32 MMAs/warp between barriers).
// EPI: 0=+bias[n]->bf16, 1=+bias[m]->bf16, 2=*alpha->f32, 3=none->bf16,
//      4=+bias[m]+res[m][n]->f32
// ---------------------------------------------------------------------------
constexpr int kRowW   = 16;              // words per tile row (32 bf16)
constexpr int kTileW  = 128 * kRowW;     // 2048 words = 8 KB per tile
constexpr int kStageW = 2 * kTileW;      // A + B = 16 KB per stage
constexpr int kNS     = 3;               // stages (48 KB total)

__device__ __forceinline__ uint32_t swoff(int row, int c) {
    // word offset of 16B chunk c in swizzled tile (row = 64B)
    return (uint32_t)(row * kRowW + ((c ^ ((row >> 1) & 3)) << 2));
}

template <int EPI>
__global__ void __launch_bounds__(256, 2)
gemm_bf16(const __nv_bfloat16* __restrict__ A, const __nv_bfloat16* __restrict__ B,
          const float* __restrict__ bias, const float* __restrict__ res,
          void* __restrict__ Cv,
          int lda, int ldb, int ldc, int K,
          size_t sA, size_t sB, size_t sC, float alpha) {
    __shared__ __align__(16) uint32_t sm[kNS * kStageW];   // 49,152 bytes
    const int tid = threadIdx.x;
    const int lane = tid & 31, wid = tid >> 5;
    const int wm = wid & 1, wn = wid >> 1;   // warp grid 2 x 4

    const int bz = blockIdx.z;
    const __nv_bfloat16* Ab = A + sA * bz;
    const __nv_bfloat16* Bb = B + sB * bz;
    const int m0 = blockIdx.y * 128;
    const int n0 = blockIdx.x * 128;

    const uint32_t smAddr = smem_u32(sm);
    const int KT = K / 32;

    // ldmatrix lane decomposition (mapping verified in Round 7)
    const int lg   = lane >> 3;          // lane group 0..3
    const int lrow = lane & 7;
    const int aRow = wm * 64 + (lg & 1) * 8 + lrow;   // + mt*16
    const int aChk = lg >> 1;                          // + kk*2
    const int bRow = wn * 32 + (lg >> 1) * 8 + lrow;  // + j*16
    const int bChk = lg & 1;                           // + kk*2

    // prefetch k-block it into stage s: 4 cp16 per thread (2 A + 2 B)
    auto prefetch = [&](int it, int s) {
        const int k0 = it * 32;
        const uint32_t aBase = smAddr + (uint32_t)(s * kStageW) * 4u;
        const uint32_t bBase = aBase + (uint32_t)kTileW * 4u;
        #pragma unroll
        for (int t = 0; t < 2; t++) {
            const int idx = t * 256 + tid;   // 0..511
            const int row = idx >> 2, c = idx & 3;
            const uint32_t off = swoff(row, c) * 4u;
            cp16(aBase + off, Ab + (size_t)(m0 + row) * lda + k0 + c * 8);
            cp16(bBase + off, Bb + (size_t)(n0 + row) * ldb + k0 + c * 8);
        }
    };

    float acc[4][4][4];
    #pragma unroll
    for (int i = 0; i < 4; i++)
        #pragma unroll
        for (int j = 0; j < 4; j++)
            #pragma unroll
            for (int r = 0; r < 4; r++) acc[i][j][r] = 0.f;

    prefetch(0, 0); cp_commit();
    prefetch(1, 1); cp_commit();

    for (int it = 0; it < KT; ++it) {
        cp_wait<1>();                // stage it%3 resident
        __syncthreads();             // all warps done reading stage (it+2)%3

        if (it + 2 < KT) prefetch(it + 2, (it + 2) % kNS);
        cp_commit();

        const uint32_t aTile = smAddr + (uint32_t)((it % kNS) * kStageW) * 4u;
        const uint32_t bTile = aTile + (uint32_t)kTileW * 4u;

        #pragma unroll
        for (int kk = 0; kk < 2; kk++) {
            uint32_t af[4][4];
            #pragma unroll
            for (int mt = 0; mt < 4; mt++)
                ldsm4(af[mt], aTile +
                      swoff(aRow + mt * 16, aChk + kk * 2) * 4u);
            uint32_t bf[4][2];
            #pragma unroll
            for (int j = 0; j < 2; j++)
                ldsm4(&bf[2 * j][0], bTile +
                      swoff(bRow + j * 16, bChk + kk * 2) * 4u);
            #pragma unroll
            for (int mt = 0; mt < 4; mt++)
                #pragma unroll
                for (int nt = 0; nt < 4; nt++)
                    mma16(acc[mt][nt], af[mt], bf[nt]);
        }
    }

    // ---- epilogue ----
    constexpr bool OUTB = (EPI == 0 || EPI == 1 || EPI == 3);
    const int rA = lane >> 2, cA = lane & 3;
    #pragma unroll
    for (int mt = 0; mt < 4; mt++) {
        const int r0 = m0 + wm * 64 + mt * 16 + rA;
        float bm0 = 0.f, bm1 = 0.f;
        if (EPI == 1 || EPI == 4) { bm0 = bias[r0]; bm1 = bias[r0 + 8]; }
        #pragma unroll
        for (int nt = 0; nt < 4; nt++) {
            const int col = n0 + wn * 32 + nt * 8 + cA * 2;
            float d0 = acc[mt][nt][0], d1 = acc[mt][nt][1];
            float d2 = acc[mt][nt][2], d3 = acc[mt][nt][3];
            if (EPI == 0) {
                const float b0 = bias[col], b1 = bias[col + 1];
                d0 += b0; d1 += b1; d2 += b0; d3 += b1;
            } else if (EPI == 1 || EPI == 4) {
                d0 += bm0; d1 += bm0; d2 += bm1; d3 += bm1;
            } else if (EPI == 2) {
                d0 *= alpha; d1 *= alpha; d2 *= alpha; d3 *= alpha;
            }
            if (EPI == 4) {
                const float* rp = res + sC * bz;
                d0 += rp[(size_t)r0 * ldc + col];
                d1 += rp[(size_t)r0 * ldc + col + 1];
                d2 += rp[(size_t)(r0 + 8) * ldc + col];
                d3 += rp[(size_t)(r0 + 8) * ldc + col + 1];
            }
            if (OUTB) {
                __nv_bfloat16* Cb = (__nv_bfloat16*)Cv + sC * bz;
                *(__nv_bfloat162*)(Cb + (size_t)r0 * ldc + col) =
                    __floats2bfloat162_rn(d0, d1);
                *(__nv_bfloat162*)(Cb + (size_t)(r0 + 8) * ldc + col) =
                    __floats2bfloat162_rn(d2, d3);
            } else {
                float* Cb = (float*)Cv + sC * bz;
                *(float2*)(Cb + (size_t)r0 * ldc + col)       = make_float2(d0, d1);
                *(float2*)(Cb + (size_t)(r0 + 8) * ldc + col) = make_float2(d2, d3);
            }
        }
    }
}

// ---------------------------------------------------------------------------
// Row softmax over 4096 f32 logits -> bf16 attn; one block (256 thr) per row.
// ---------------------------------------------------------------------------
__global__ void softmax_kernel(const float* __restrict__ sim,
                               __nv_bfloat16* __restrict__ simh) {
    const float* p = sim + (size_t)blockIdx.x * kHW;
    __nv_bfloat16* ph = simh + (size_t)blockIdx.x * kHW;
    const int tid = threadIdx.x;
    float v[16];
    float mx = -1e30f;
    #pragma unroll
    for (int i = 0; i < 16; i++) {
        v[i] = p[tid + i * 256];
        mx = fmaxf(mx, v[i]);
    }
    __shared__ float sh[256];
    sh[tid] = mx; __syncthreads();
    for (int o = 128; o > 0; o >>= 1) {
        if (tid < o) sh[tid] = fmaxf(sh[tid], sh[tid + o]);
        __syncthreads();
    }
    mx = sh[0];
    __syncthreads();
    float s = 0.f;
    #pragma unroll
    for (int i = 0; i < 16; i++) { v[i] = __expf(v[i] - mx); s += v[i]; }
    sh[tid] = s; __syncthreads();
    for (int o = 128; o > 0; o >>= 1) {
        if (tid < o) sh[tid] += sh[tid + o];
        __syncthreads();
    }
    const float rinv = 1.f / sh[0];
    #pragma unroll
    for (int i = 0; i < 16; i++)
        ph[tid + i * 256] = __float2bfloat16_rn(v[i] * rinv);
}

// ---------------------------------------------------------------------------
extern "C" void kernel_launch(void* const* d_in, const int* in_sizes, int n_in,
                              void* d_out, int out_size) {
    const float* x     = (const float*)d_in[0];
    const float* gamma = (const float*)d_in[1];
    const float* beta  = (const float*)d_in[2];
    const float* wq    = (const float*)d_in[3];
    const float* bq    = (const float*)d_in[4];
    const float* wk    = (const float*)d_in[5];
    const float* bk    = (const float*)d_in[6];
    const float* wv    = (const float*)d_in[7];
    const float* bv    = (const float*)d_in[8];
    const float* wo    = (const float*)d_in[9];
    const float* bo    = (const float*)d_in[10];
    float* out = (float*)d_out;

    __nv_bfloat16 *hT, *qt, *kt, *v, *o2, *simh, *wh;
    float *sim, *aff;
    cudaGetSymbolAddress((void**)&hT,   g_hT);
    cudaGetSymbolAddress((void**)&qt,   g_qt);
    cudaGetSymbolAddress((void**)&kt,   g_kt);
    cudaGetSymbolAddress((void**)&v,    g_v);
    cudaGetSymbolAddress((void**)&o2,   g_o2);
    cudaGetSymbolAddress((void**)&sim,  g_sim);
    cudaGetSymbolAddress((void**)&simh, g_simh);
    cudaGetSymbolAddress((void**)&aff,  g_aff);
    cudaGetSymbolAddress((void**)&wh,   g_wh);

    const size_t sNC = (size_t)kHW * kC;    // per-batch [n][c] / [c][n]
    const size_t sNN = (size_t)kHW * kHW;   // per-batch sim
    const float  scale = 1.0f / sqrtf((float)kC);
    const int nW = kC * kC;

    // 0) weights -> bf16
    prep_weights<<<(nW + 255) / 256, 256>>>(wq, wk, wv, wo, wh);

    // 1) GroupNorm (stats + fused normalize-transpose-bf16)
    gn_stats<<<kB * kG, 256>>>(x, gamma, beta, aff);
    gn_norm_t<<<dim3(kHW / 32, kC / 32, kB), dim3(32, 8)>>>(x, aff, hT);

    // 2) Qt / Kt = hT @ W^T  (M=4096, N=512, K=512), bias over columns
    {
        dim3 grid(kC / 128, kHW / 128, kB);
        gemm_bf16<0><<<grid, 256>>>(hT, wh + 0 * nW, bq, nullptr, qt,
                                    kC, kC, kC, kC, sNC, 0, sNC, 1.f);
        gemm_bf16<0><<<grid, 256>>>(hT, wh + 1 * nW, bk, nullptr, kt,
                                    kC, kC, kC, kC, sNC, 0, sNC, 1.f);
    }
    // 3) V = Wv @ H  (M=512, N=4096, K=512), output [c][n], bias over rows
    {
        dim3 grid(kHW / 128, kC / 128, kB);
        gemm_bf16<1><<<grid, 256>>>(wh + 2 * nW, hT, bv, nullptr, v,
                                    kC, kC, kHW, kC, 0, sNC, sNC, 1.f);
    }
    // 4) sim = Qt @ Kt^T * scale  (M=N=4096, K=512), f32 out
    {
        dim3 grid(kHW / 128, kHW / 128, kB);
        gemm_bf16<2><<<grid, 256>>>(qt, kt, nullptr, nullptr, sim,
                                    kC, kC, kHW, kC, sNC, sNC, sNN, scale);
    }
    // 5) softmax rows -> bf16
    softmax_kernel<<<kB * kHW, 256>>>(sim, simh);

    // 6) o2 = attn @ V^T  (M=4096, N=512, K=4096), output [n][c] bf16
    {
        dim3 grid(kC / 128, kHW / 128, kB);
        gemm_bf16<3><<<grid, 256>>>(simh, v, nullptr, nullptr, o2,
                                    kHW, kHW, kC, kHW, sNN, sNC, sNC, 1.f);
    }
    // 7) out = x + Wo @ o2^T + bo  (M=512, N=4096, K=512), f32 out
    {
        dim3 grid(kHW / 128, kC / 128, kB);
        gemm_bf16<4><<<grid, 256>>>(wh + 3 * nW, o2, bo, x, out,
                                    kC, kC, kHW, kC, 0, sNC, sNC, 1.f);
    }
}

// round 10
// speedup vs baseline: 7.3444x; 1.1055x over previous
#include <cuda_runtime.h>
#include <cuda_bf16.h>
#include <cstdint>
#include <math.h>

// ---------------------------------------------------------------------------
// Problem constants
// ---------------------------------------------------------------------------
constexpr int kB  = 4;
constexpr int kC  = 512;
constexpr int kHW = 4096;
constexpr int kG  = 32;
constexpr int kCPG = kC / kG;   // 16
constexpr float kEPS = 1e-6f;

// Scratch (__device__ globals per allocation-free rule)
__device__ __nv_bfloat16 g_hT [(size_t)kB * kHW * kC];   // GN out [b][n][c]
__device__ __nv_bfloat16 g_qt [(size_t)kB * kHW * kC];   // Q^T [b][n][c]
__device__ __nv_bfloat16 g_kt [(size_t)kB * kHW * kC];   // K^T [b][n][c]
__device__ __nv_bfloat16 g_v  [(size_t)kB * kC * kHW];   // V   [b][c][n]
__device__ __nv_bfloat16 g_o2 [(size_t)kB * kHW * kC];   // attn@V [b][n][c]
__device__ __nv_bfloat16 g_simh[(size_t)kB * kHW * kHW]; // P~ = exp(logit) bf16
__device__ float         g_rs [(size_t)kB * kHW];        // softmax row sums
__device__ float         g_aff[(size_t)kB * kC * 2];     // (scale, offset)
__device__ __nv_bfloat16 g_wh [4 * kC * kC];             // bf16 wq,wk,wv,wo

// ---------------------------------------------------------------------------
// Helpers
// ---------------------------------------------------------------------------
__device__ __forceinline__ uint32_t smem_u32(const void* p) {
    uint32_t a;
    asm("{ .reg .u64 t; cvta.to.shared.u64 t, %1; cvt.u32.u64 %0, t; }"
        : "=r"(a) : "l"(p));
    return a;
}
__device__ __forceinline__ void cp16(uint32_t dst, const void* src) {
    asm volatile("cp.async.cg.shared.global [%0], [%1], 16;\n"
                 :: "r"(dst), "l"(src));
}
__device__ __forceinline__ void cp_commit() {
    asm volatile("cp.async.commit_group;\n" ::: "memory");
}
template <int N>
__device__ __forceinline__ void cp_wait() {
    asm volatile("cp.async.wait_group %0;\n" :: "n"(N) : "memory");
}
// m16n8k16 bf16 mma, row.col, fp32 accum
__device__ __forceinline__ void mma16(float* d, const uint32_t* a, const uint32_t* b) {
    asm volatile(
        "mma.sync.aligned.m16n8k16.row.col.f32.bf16.bf16.f32 "
        "{%0,%1,%2,%3}, {%4,%5,%6,%7}, {%8,%9}, {%0,%1,%2,%3};"
        : "+f"(d[0]), "+f"(d[1]), "+f"(d[2]), "+f"(d[3])
        : "r"(a[0]), "r"(a[1]), "r"(a[2]), "r"(a[3]), "r"(b[0]), "r"(b[1]));
}
// ldmatrix 4x (m8n8 b16)
__device__ __forceinline__ void ldsm4(uint32_t* r, uint32_t addr) {
    asm volatile(
        "ldmatrix.sync.aligned.m8n8.x4.shared.b16 {%0,%1,%2,%3}, [%4];"
        : "=r"(r[0]), "=r"(r[1]), "=r"(r[2]), "=r"(r[3]) : "r"(addr));
}

// ---------------------------------------------------------------------------
// Weight prep: round 4 weight matrices to bf16
// ---------------------------------------------------------------------------
__global__ void prep_weights(const float* __restrict__ wq, const float* __restrict__ wk,
                             const float* __restrict__ wv, const float* __restrict__ wo,
                             __nv_bfloat16* __restrict__ wh) {
    const int i = blockIdx.x * blockDim.x + threadIdx.x;
    const int n = kC * kC;
    if (i < n) {
        wh[0 * n + i] = __float2bfloat16_rn(wq[i]);
        wh[1 * n + i] = __float2bfloat16_rn(wk[i]);
        wh[2 * n + i] = __float2bfloat16_rn(wv[i]);
        wh[3 * n + i] = __float2bfloat16_rn(wo[i]);
    }
}

// Zero the softmax row-sum accumulators (graph-replay safe)
__global__ void rs_init(float* __restrict__ rs) {
    rs[blockIdx.x * 256 + threadIdx.x] = 0.f;
}

// ---------------------------------------------------------------------------
// GroupNorm pass 1: per-(b,g) mean/var -> per-channel affine (a, b)
// ---------------------------------------------------------------------------
__global__ void gn_stats(const float* __restrict__ x,
                         const float* __restrict__ gamma,
                         const float* __restrict__ beta,
                         float* __restrict__ aff) {
    const int b = blockIdx.x / kG, g = blockIdx.x % kG;
    const float* xp = x + ((size_t)b * kC + (size_t)g * kCPG) * kHW;
    const int N = kCPG * kHW;

    float s = 0.f, ss = 0.f;
    for (int i = threadIdx.x; i < N; i += 256) {
        float v = xp[i];
        s += v; ss += v * v;
    }
    __shared__ float sh1[256], sh2[256];
    sh1[threadIdx.x] = s; sh2[threadIdx.x] = ss;
    __syncthreads();
    for (int o = 128; o > 0; o >>= 1) {
        if (threadIdx.x < o) {
            sh1[threadIdx.x] += sh1[threadIdx.x + o];
            sh2[threadIdx.x] += sh2[threadIdx.x + o];
        }
        __syncthreads();
    }
    if (threadIdx.x < kCPG) {
        const float mean = sh1[0] / (float)N;
        const float var  = sh2[0] / (float)N - mean * mean;
        const float rinv = rsqrtf(var + kEPS);
        const int ch = g * kCPG + threadIdx.x;
        const float a = rinv * gamma[ch];
        aff[((size_t)b * kC + ch) * 2 + 0] = a;
        aff[((size_t)b * kC + ch) * 2 + 1] = beta[ch] - mean * a;
    }
}

// ---------------------------------------------------------------------------
// GroupNorm pass 2: normalize + transpose + bf16: x[b][c][n] -> hT[b][n][c]
// ---------------------------------------------------------------------------
__global__ void gn_norm_t(const float* __restrict__ x,
                          const float* __restrict__ aff,
                          __nv_bfloat16* __restrict__ hT) {
    __shared__ float t[32][33];
    const int b = blockIdx.z;
    const int n0 = blockIdx.x * 32, c0 = blockIdx.y * 32;
    const int tx = threadIdx.x, ty = threadIdx.y;   // 32 x 8
    const float* xb = x  + (size_t)b * kC * kHW;
    __nv_bfloat16* hb = hT + (size_t)b * kHW * kC;

    #pragma unroll
    for (int r = 0; r < 4; r++) {
        const int c = c0 + ty + r * 8;
        const float a  = aff[((size_t)b * kC + c) * 2 + 0];
        const float bb = aff[((size_t)b * kC + c) * 2 + 1];
        t[ty + r * 8][tx] = xb[(size_t)c * kHW + n0 + tx] * a + bb;
    }
    __syncthreads();
    #pragma unroll
    for (int r = 0; r < 4; r++) {
        const int n = n0 + ty + r * 8;
        hb[(size_t)n * kC + c0 + tx] = __float2bfloat16_rn(t[tx][ty + r * 8]);
    }
}

// ---------------------------------------------------------------------------
// bf16 mma.sync GEMM: C[m][n] = sum_k A[m][k] * B[n][k]  (both K-major bf16)
// 128x128x32 tile, 3-stage cp.async pipeline, swizzled smem, 48KB static.
// 256 threads, 8 warps (2x4), warp tile 64x32. 2 CTAs/SM.
// EPI: 0=+bias[n]->bf16, 1=+bias[m]->bf16,
//      2=exp(alpha*acc)->bf16 + atomic row-sum into res (softmax numerator),
//      4=+bias[m]+res[m][n]->f32,
//      5=acc/rowsum[m]->bf16 (bias = rowsum base, per-batch kHW stride)
// ---------------------------------------------------------------------------
constexpr int kRowW   = 16;              // words per tile row (32 bf16)
constexpr int kTileW  = 128 * kRowW;     // 2048 words = 8 KB per tile
constexpr int kStageW = 2 * kTileW;      // A + B = 16 KB per stage
constexpr int kNS     = 3;               // stages (48 KB total)

__device__ __forceinline__ uint32_t swoff(int row, int c) {
    // word offset of 16B chunk c in swizzled tile (row = 64B)
    return (uint32_t)(row * kRowW + ((c ^ ((row >> 1) & 3)) << 2));
}

template <int EPI>
__global__ void __launch_bounds__(256, 2)
gemm_bf16(const __nv_bfloat16* __restrict__ A, const __nv_bfloat16* __restrict__ B,
          const float* __restrict__ bias, float* __restrict__ res,
          void* __restrict__ Cv,
          int lda, int ldb, int ldc, int K,
          size_t sA, size_t sB, size_t sC, float alpha) {
    __shared__ __align__(16) uint32_t sm[kNS * kStageW];   // 49,152 bytes
    const int tid = threadIdx.x;
    const int lane = tid & 31, wid = tid >> 5;
    const int wm = wid & 1, wn = wid >> 1;   // warp grid 2 x 4

    const int bz = blockIdx.z;
    const __nv_bfloat16* Ab = A + sA * bz;
    const __nv_bfloat16* Bb = B + sB * bz;
    const int m0 = blockIdx.y * 128;
    const int n0 = blockIdx.x * 128;

    const uint32_t smAddr = smem_u32(sm);
    const int KT = K / 32;

    // ldmatrix lane decomposition (mapping verified in Round 7)
    const int lg   = lane >> 3;          // lane group 0..3
    const int lrow = lane & 7;
    const int aRow = wm * 64 + (lg & 1) * 8 + lrow;   // + mt*16
    const int aChk = lg >> 1;                          // + kk*2
    const int bRow = wn * 32 + (lg >> 1) * 8 + lrow;  // + j*16
    const int bChk = lg & 1;                           // + kk*2

    // prefetch k-block it into stage s: 4 cp16 per thread (2 A + 2 B)
    auto prefetch = [&](int it, int s) {
        const int k0 = it * 32;
        const uint32_t aBase = smAddr + (uint32_t)(s * kStageW) * 4u;
        const uint32_t bBase = aBase + (uint32_t)kTileW * 4u;
        #pragma unroll
        for (int t = 0; t < 2; t++) {
            const int idx = t * 256 + tid;   // 0..511
            const int row = idx >> 2, c = idx & 3;
            const uint32_t off = swoff(row, c) * 4u;
            cp16(aBase + off, Ab + (size_t)(m0 + row) * lda + k0 + c * 8);
            cp16(bBase + off, Bb + (size_t)(n0 + row) * ldb + k0 + c * 8);
        }
    };

    float acc[4][4][4];
    #pragma unroll
    for (int i = 0; i < 4; i++)
        #pragma unroll
        for (int j = 0; j < 4; j++)
            #pragma unroll
            for (int r = 0; r < 4; r++) acc[i][j][r] = 0.f;

    prefetch(0, 0); cp_commit();
    prefetch(1, 1); cp_commit();

    for (int it = 0; it < KT; ++it) {
        cp_wait<1>();                // stage it%3 resident
        __syncthreads();             // all warps done reading stage (it+2)%3

        if (it + 2 < KT) prefetch(it + 2, (it + 2) % kNS);
        cp_commit();

        const uint32_t aTile = smAddr + (uint32_t)((it % kNS) * kStageW) * 4u;
        const uint32_t bTile = aTile + (uint32_t)kTileW * 4u;

        #pragma unroll
        for (int kk = 0; kk < 2; kk++) {
            uint32_t af[4][4];
            #pragma unroll
            for (int mt = 0; mt < 4; mt++)
                ldsm4(af[mt], aTile +
                      swoff(aRow + mt * 16, aChk + kk * 2) * 4u);
            uint32_t bf[4][2];
            #pragma unroll
            for (int j = 0; j < 2; j++)
                ldsm4(&bf[2 * j][0], bTile +
                      swoff(bRow + j * 16, bChk + kk * 2) * 4u);
            #pragma unroll
            for (int mt = 0; mt < 4; mt++)
                #pragma unroll
                for (int nt = 0; nt < 4; nt++)
                    mma16(acc[mt][nt], af[mt], bf[nt]);
        }
    }

    // ---- epilogue ----
    const int rA = lane >> 2, cA = lane & 3;

    if constexpr (EPI == 2) {
        // exp(alpha * acc) -> bf16 P~; atomic row-sum of rounded values
        __nv_bfloat16* Cb = (__nv_bfloat16*)Cv + sC * bz;
        float* rs = res + (size_t)bz * kHW;
        #pragma unroll
        for (int mt = 0; mt < 4; mt++) {
            const int r0 = m0 + wm * 64 + mt * 16 + rA;
            float s0 = 0.f, s1 = 0.f;
            #pragma unroll
            for (int nt = 0; nt < 4; nt++) {
                const int col = n0 + wn * 32 + nt * 8 + cA * 2;
                const float e0 = __expf(acc[mt][nt][0] * alpha);
                const float e1 = __expf(acc[mt][nt][1] * alpha);
                const float e2 = __expf(acc[mt][nt][2] * alpha);
                const float e3 = __expf(acc[mt][nt][3] * alpha);
                const __nv_bfloat162 w0 = __floats2bfloat162_rn(e0, e1);
                const __nv_bfloat162 w1 = __floats2bfloat162_rn(e2, e3);
                *(__nv_bfloat162*)(Cb + (size_t)r0 * ldc + col)       = w0;
                *(__nv_bfloat162*)(Cb + (size_t)(r0 + 8) * ldc + col) = w1;
                s0 += __low2float(w0) + __high2float(w0);
                s1 += __low2float(w1) + __high2float(w1);
            }
            // reduce over the 4 cA lanes (lane = rA*4 + cA)
            s0 += __shfl_xor_sync(0xffffffffu, s0, 1);
            s0 += __shfl_xor_sync(0xffffffffu, s0, 2);
            s1 += __shfl_xor_sync(0xffffffffu, s1, 1);
            s1 += __shfl_xor_sync(0xffffffffu, s1, 2);
            if (cA == 0) {
                atomicAdd(&rs[r0], s0);
                atomicAdd(&rs[r0 + 8], s1);
            }
        }
        return;
    }

    constexpr bool OUTB = (EPI == 0 || EPI == 1 || EPI == 5);
    #pragma unroll
    for (int mt = 0; mt < 4; mt++) {
        const int r0 = m0 + wm * 64 + mt * 16 + rA;
        float bm0 = 0.f, bm1 = 0.f;
        if (EPI == 1 || EPI == 4) { bm0 = bias[r0]; bm1 = bias[r0 + 8]; }
        if (EPI == 5) {
            bm0 = 1.f / bias[(size_t)bz * kHW + r0];
            bm1 = 1.f / bias[(size_t)bz * kHW + r0 + 8];
        }
        #pragma unroll
        for (int nt = 0; nt < 4; nt++) {
            const int col = n0 + wn * 32 + nt * 8 + cA * 2;
            float d0 = acc[mt][nt][0], d1 = acc[mt][nt][1];
            float d2 = acc[mt][nt][2], d3 = acc[mt][nt][3];
            if (EPI == 0) {
                const float b0 = bias[col], b1 = bias[col + 1];
                d0 += b0; d1 += b1; d2 += b0; d3 += b1;
            } else if (EPI == 1 || EPI == 4) {
                d0 += bm0; d1 += bm0; d2 += bm1; d3 += bm1;
            } else if (EPI == 5) {
                d0 *= bm0; d1 *= bm0; d2 *= bm1; d3 *= bm1;
            }
            if (EPI == 4) {
                const float* rp = res + sC * bz;
                d0 += rp[(size_t)r0 * ldc + col];
                d1 += rp[(size_t)r0 * ldc + col + 1];
                d2 += rp[(size_t)(r0 + 8) * ldc + col];
                d3 += rp[(size_t)(r0 + 8) * ldc + col + 1];
            }
            if (OUTB) {
                __nv_bfloat16* Cb = (__nv_bfloat16*)Cv + sC * bz;
                *(__nv_bfloat162*)(Cb + (size_t)r0 * ldc + col) =
                    __floats2bfloat162_rn(d0, d1);
                *(__nv_bfloat162*)(Cb + (size_t)(r0 + 8) * ldc + col) =
                    __floats2bfloat162_rn(d2, d3);
            } else {
                float* Cb = (float*)Cv + sC * bz;
                *(float2*)(Cb + (size_t)r0 * ldc + col)       = make_float2(d0, d1);
                *(float2*)(Cb + (size_t)(r0 + 8) * ldc + col) = make_float2(d2, d3);
            }
        }
    }
}

// ---------------------------------------------------------------------------
extern "C" void kernel_launch(void* const* d_in, const int* in_sizes, int n_in,
                              void* d_out, int out_size) {
    const float* x     = (const float*)d_in[0];
    const float* gamma = (const float*)d_in[1];
    const float* beta  = (const float*)d_in[2];
    const float* wq    = (const float*)d_in[3];
    const float* bq    = (const float*)d_in[4];
    const float* wk    = (const float*)d_in[5];
    const float* bk    = (const float*)d_in[6];
    const float* wv    = (const float*)d_in[7];
    const float* bv    = (const float*)d_in[8];
    const float* wo    = (const float*)d_in[9];
    const float* bo    = (const float*)d_in[10];
    float* out = (float*)d_out;

    __nv_bfloat16 *hT, *qt, *kt, *v, *o2, *simh, *wh;
    float *aff, *rs;
    cudaGetSymbolAddress((void**)&hT,   g_hT);
    cudaGetSymbolAddress((void**)&qt,   g_qt);
    cudaGetSymbolAddress((void**)&kt,   g_kt);
    cudaGetSymbolAddress((void**)&v,    g_v);
    cudaGetSymbolAddress((void**)&o2,   g_o2);
    cudaGetSymbolAddress((void**)&simh, g_simh);
    cudaGetSymbolAddress((void**)&aff,  g_aff);
    cudaGetSymbolAddress((void**)&rs,   g_rs);
    cudaGetSymbolAddress((void**)&wh,   g_wh);

    const size_t sNC = (size_t)kHW * kC;    // per-batch [n][c] / [c][n]
    const size_t sNN = (size_t)kHW * kHW;   // per-batch sim
    const float  scale = 1.0f / sqrtf((float)kC);
    const int nW = kC * kC;

    // 0) weights -> bf16; zero row sums
    prep_weights<<<(nW + 255) / 256, 256>>>(wq, wk, wv, wo, wh);
    rs_init<<<kB * kHW / 256, 256>>>(rs);

    // 1) GroupNorm (stats + fused normalize-transpose-bf16)
    gn_stats<<<kB * kG, 256>>>(x, gamma, beta, aff);
    gn_norm_t<<<dim3(kHW / 32, kC / 32, kB), dim3(32, 8)>>>(x, aff, hT);

    // 2) Qt / Kt = hT @ W^T  (M=4096, N=512, K=512), bias over columns
    {
        dim3 grid(kC / 128, kHW / 128, kB);
        gemm_bf16<0><<<grid, 256>>>(hT, wh + 0 * nW, bq, nullptr, qt,
                                    kC, kC, kC, kC, sNC, 0, sNC, 1.f);
        gemm_bf16<0><<<grid, 256>>>(hT, wh + 1 * nW, bk, nullptr, kt,
                                    kC, kC, kC, kC, sNC, 0, sNC, 1.f);
    }
    // 3) V = Wv @ H  (M=512, N=4096, K=512), output [c][n], bias over rows
    {
        dim3 grid(kHW / 128, kC / 128, kB);
        gemm_bf16<1><<<grid, 256>>>(wh + 2 * nW, hT, bv, nullptr, v,
                                    kC, kC, kHW, kC, 0, sNC, sNC, 1.f);
    }
    // 4) P~ = exp(scale * Qt@Kt^T) -> bf16, + row sums (M=N=4096, K=512)
    {
        dim3 grid(kHW / 128, kHW / 128, kB);
        gemm_bf16<2><<<grid, 256>>>(qt, kt, nullptr, rs, simh,
                                    kC, kC, kHW, kC, sNC, sNC, sNN, scale);
    }
    // 5) o2 = (P~ @ V^T) / rowsum  (M=4096, N=512, K=4096), output [n][c] bf16
    {
        dim3 grid(kC / 128, kHW / 128, kB);
        gemm_bf16<5><<<grid, 256>>>(simh, v, rs, nullptr, o2,
                                    kHW, kHW, kC, kHW, sNN, sNC, sNC, 1.f);
    }
    // 6) out = x + Wo @ o2^T + bo  (M=512, N=4096, K=512), f32 out
    {
        dim3 grid(kHW / 128, kC / 128, kB);
        gemm_bf16<4><<<grid, 256>>>(wh + 3 * nW, o2, bo, (float*)x, out,
                                    kC, kC, kHW, kC, 0, sNC, sNC, 1.f);
    }
}